// round 1
// baseline (speedup 1.0000x reference)
#include <cuda_runtime.h>
#include <math.h>

#define TOK 8192
#define SEQB 4096
#define DDIM 2560
#define KDIM 2560
#define HEADS 10
#define BW 256
#define NC 32
#define CL 128

// ---------------- scratch (static device globals; no allocation) ----------------
__device__ float g_xb[(size_t)TOK * DDIM];   // x-branch (pre-conv)
__device__ float g_yb[(size_t)TOK * DDIM];   // gelu(y-branch)
__device__ float g_co[(size_t)TOK * DDIM];   // conv output
__device__ float g_a [(size_t)TOK * DDIM];   // recurrence decay a_t
__device__ float g_nx[(size_t)TOK * DDIM];   // normalized x; later h*y
__device__ float g_Aag[2 * NC * DDIM];
__device__ float g_Hag[2 * NC * DDIM];
__device__ float g_Hin[2 * NC * DDIM];
__device__ unsigned char g_reset[TOK];

// ---------------- helpers ----------------
__device__ __forceinline__ float gelu_tanh(float x) {
    float x3 = x * x * x;
    float t = tanhf(0.7978845608028654f * (x + 0.044715f * x3));
    return 0.5f * x * (1.0f + t);
}
__device__ __forceinline__ float sigmoidf(float x) {
    return 1.0f / (1.0f + expf(-x));
}
__device__ __forceinline__ float softplusf(float x) {
    return (x > 20.0f) ? x : log1pf(expf(x));
}

// ---------------- reset-mask kernel (handles int32 or int64 position_ids) ----------------
__global__ void reset_kernel(const int* __restrict__ pos32) {
    int m = blockIdx.x * 256 + threadIdx.x;
    if (m >= TOK) return;
    // arange layout probe: int32 => [0,1,2,...]; int64(LE) => [0,0,1,0,2,0,...]
    bool is64 = (pos32[1] == 0 && pos32[2] == 1);
    bool r;
    if (is64) r = (pos32[2 * m] == 0 && pos32[2 * m + 1] == 0);
    else      r = (pos32[m] == 0);
    g_reset[m] = r ? 1 : 0;
}

// ---------------- 128x128x8 fp32 SGEMM: C[m,n] = sum_k A[m,k]*W[n,k] + bias[n] ----------------
// A: [TOK x KDIM] row-major, W: [DDIM x KDIM] row-major, C: [TOK x DDIM]
__global__ __launch_bounds__(256) void sgemm128(const float* __restrict__ A,
                                                const float* __restrict__ W,
                                                const float* __restrict__ bias,
                                                float* __restrict__ C,
                                                int do_gelu) {
    __shared__ float As[8][128];
    __shared__ float Bs[8][128];
    const int tid = threadIdx.x;
    const int m0 = blockIdx.y * 128;
    const int n0 = blockIdx.x * 128;
    const int lrow = tid >> 1;
    const int lk = (tid & 1) * 4;
    const float* Ap = A + (size_t)(m0 + lrow) * KDIM + lk;
    const float* Wp = W + (size_t)(n0 + lrow) * KDIM + lk;
    const int ty = tid >> 4;
    const int tx = tid & 15;

    float acc[8][8];
#pragma unroll
    for (int i = 0; i < 8; i++)
#pragma unroll
        for (int j = 0; j < 8; j++) acc[i][j] = 0.0f;

    for (int k0 = 0; k0 < KDIM; k0 += 8) {
        float4 av = *(const float4*)(Ap + k0);
        float4 bv = *(const float4*)(Wp + k0);
        __syncthreads();
        As[lk + 0][lrow] = av.x; As[lk + 1][lrow] = av.y;
        As[lk + 2][lrow] = av.z; As[lk + 3][lrow] = av.w;
        Bs[lk + 0][lrow] = bv.x; Bs[lk + 1][lrow] = bv.y;
        Bs[lk + 2][lrow] = bv.z; Bs[lk + 3][lrow] = bv.w;
        __syncthreads();
#pragma unroll
        for (int k = 0; k < 8; k++) {
            float af[8], bf[8];
            *(float4*)&af[0] = *(const float4*)&As[k][ty * 8];
            *(float4*)&af[4] = *(const float4*)&As[k][ty * 8 + 4];
            *(float4*)&bf[0] = *(const float4*)&Bs[k][tx * 8];
            *(float4*)&bf[4] = *(const float4*)&Bs[k][tx * 8 + 4];
#pragma unroll
            for (int i = 0; i < 8; i++)
#pragma unroll
                for (int j = 0; j < 8; j++)
                    acc[i][j] = fmaf(af[i], bf[j], acc[i][j]);
        }
    }

#pragma unroll
    for (int i = 0; i < 8; i++) {
        int m = m0 + ty * 8 + i;
        float* Crow = C + (size_t)m * DDIM + n0 + tx * 8;
#pragma unroll
        for (int j = 0; j < 8; j++) {
            float v = acc[i][j] + bias[n0 + tx * 8 + j];
            if (do_gelu) v = gelu_tanh(v);
            Crow[j] = v;
        }
    }
}

// ---------------- depthwise causal conv (width 4) ----------------
__global__ __launch_bounds__(256) void conv_kernel(const float* __restrict__ cw,
                                                   const float* __restrict__ cb) {
    int idx = blockIdx.x * 256 + threadIdx.x;
    if (idx >= TOK * DDIM) return;
    int d = idx % DDIM;
    int m = idx / DDIM;
    int t = m & (SEQB - 1);
    float s = cb[d];
    s = fmaf(g_xb[idx], cw[d * 4 + 3], s);
    if (t >= 1) s = fmaf(g_xb[idx - DDIM],     cw[d * 4 + 2], s);
    if (t >= 2) s = fmaf(g_xb[idx - 2 * DDIM], cw[d * 4 + 1], s);
    if (t >= 3) s = fmaf(g_xb[idx - 3 * DDIM], cw[d * 4 + 0], s);
    g_co[idx] = s;
}

// ---------------- block-diagonal gates + RG-LRU pointwise ----------------
// per head h: logits[j] = sum_i co[m, h*256+i] * Wg[h*65536 + j*256 + i] + b[j]
// tile: 128 tokens x 64 outputs, both gates at once
__global__ __launch_bounds__(256) void gates_kernel(const float* __restrict__ ig_w,
                                                    const float* __restrict__ ig_b,
                                                    const float* __restrict__ ag_w,
                                                    const float* __restrict__ ag_b,
                                                    const float* __restrict__ a_param) {
    __shared__ float Xs[16][128];
    __shared__ float Wxs[16][64];
    __shared__ float Was[16][64];
    const int tid = threadIdx.x;
    const int j0 = blockIdx.x * 64;
    const int m0 = blockIdx.y * 128;
    const int h  = blockIdx.z;
    const int ty = tid >> 4;      // 0..15 -> 8 rows each
    const int tx = tid & 15;      // 0..15 -> 4 cols each

    float gx[8][4], ga[8][4];
#pragma unroll
    for (int i = 0; i < 8; i++)
#pragma unroll
        for (int j = 0; j < 4; j++) { gx[i][j] = 0.0f; ga[i][j] = 0.0f; }

    const int xrow = tid >> 1;          // 0..127
    const int xk   = (tid & 1) * 8;     // 0 or 8
    const float* Xp = g_co + (size_t)(m0 + xrow) * DDIM + h * BW + xk;
    const int wrow = (tid & 127) >> 1;  // 0..63
    const int wk   = (tid & 1) * 8;
    const float* Wg = (tid < 128) ? (ig_w + (size_t)h * 65536 + (size_t)(j0 + wrow) * 256 + wk)
                                  : (ag_w + (size_t)h * 65536 + (size_t)(j0 + wrow) * 256 + wk);

    for (int k0 = 0; k0 < BW; k0 += 16) {
        float4 x0 = *(const float4*)(Xp + k0);
        float4 x1 = *(const float4*)(Xp + k0 + 4);
        float4 w0 = *(const float4*)(Wg + k0);
        float4 w1 = *(const float4*)(Wg + k0 + 4);
        __syncthreads();
        Xs[xk + 0][xrow] = x0.x; Xs[xk + 1][xrow] = x0.y;
        Xs[xk + 2][xrow] = x0.z; Xs[xk + 3][xrow] = x0.w;
        Xs[xk + 4][xrow] = x1.x; Xs[xk + 5][xrow] = x1.y;
        Xs[xk + 6][xrow] = x1.z; Xs[xk + 7][xrow] = x1.w;
        if (tid < 128) {
            Wxs[wk + 0][wrow] = w0.x; Wxs[wk + 1][wrow] = w0.y;
            Wxs[wk + 2][wrow] = w0.z; Wxs[wk + 3][wrow] = w0.w;
            Wxs[wk + 4][wrow] = w1.x; Wxs[wk + 5][wrow] = w1.y;
            Wxs[wk + 6][wrow] = w1.z; Wxs[wk + 7][wrow] = w1.w;
        } else {
            Was[wk + 0][wrow] = w0.x; Was[wk + 1][wrow] = w0.y;
            Was[wk + 2][wrow] = w0.z; Was[wk + 3][wrow] = w0.w;
            Was[wk + 4][wrow] = w1.x; Was[wk + 5][wrow] = w1.y;
            Was[wk + 6][wrow] = w1.z; Was[wk + 7][wrow] = w1.w;
        }
        __syncthreads();
#pragma unroll
        for (int k = 0; k < 16; k++) {
            float af[8], bx[4], ba[4];
            *(float4*)&af[0] = *(const float4*)&Xs[k][ty * 8];
            *(float4*)&af[4] = *(const float4*)&Xs[k][ty * 8 + 4];
            *(float4*)&bx[0] = *(const float4*)&Wxs[k][tx * 4];
            *(float4*)&ba[0] = *(const float4*)&Was[k][tx * 4];
#pragma unroll
            for (int i = 0; i < 8; i++)
#pragma unroll
                for (int j = 0; j < 4; j++) {
                    gx[i][j] = fmaf(af[i], bx[j], gx[i][j]);
                    ga[i][j] = fmaf(af[i], ba[j], ga[i][j]);
                }
        }
    }

    // epilogue: RG-LRU pointwise
#pragma unroll
    for (int i = 0; i < 8; i++) {
        int m = m0 + ty * 8 + i;
        bool r = (g_reset[m] != 0);
#pragma unroll
        for (int jj = 0; jj < 4; jj++) {
            int j = j0 + tx * 4 + jj;
            int d = h * BW + j;
            float gxs = sigmoidf(gx[i][jj] + ig_b[j]);
            float gas = sigmoidf(ga[i][jj] + ag_b[j]);
            float log_a = -8.0f * gas * softplusf(a_param[d]);
            float a = expf(log_a);
            float mult = r ? 1.0f : sqrtf(fmaxf(1.0f - expf(2.0f * log_a), 0.0f));
            size_t o = (size_t)m * DDIM + d;
            float co = g_co[o];
            g_nx[o] = co * gxs * mult;
            g_a[o]  = r ? 0.0f : a;
        }
    }
}

// ---------------- chunked linear scan ----------------
__global__ __launch_bounds__(256) void scan_phase1() {
    int d = blockIdx.x * 256 + threadIdx.x;
    int c = blockIdx.y;
    int b = blockIdx.z;
    int base = (b * SEQB + c * CL) * DDIM + d;
    float A = 1.0f, H = 0.0f;
#pragma unroll 4
    for (int i = 0; i < CL; i++) {
        float a = g_a[base + i * DDIM];
        float x = g_nx[base + i * DDIM];
        H = fmaf(a, H, x);
        A *= a;
    }
    int o = (b * NC + c) * DDIM + d;
    g_Aag[o] = A;
    g_Hag[o] = H;
}

__global__ __launch_bounds__(256) void scan_phase2(const float* __restrict__ prev_h) {
    int t = blockIdx.x * 256 + threadIdx.x;
    if (t >= 2 * DDIM) return;
    int b = t / DDIM, d = t % DDIM;
    float h = prev_h[t];
#pragma unroll
    for (int c = 0; c < NC; c++) {
        int o = (b * NC + c) * DDIM + d;
        g_Hin[o] = h;
        h = fmaf(g_Aag[o], h, g_Hag[o]);
    }
}

__global__ __launch_bounds__(256) void scan_phase3() {
    int d = blockIdx.x * 256 + threadIdx.x;
    int c = blockIdx.y;
    int b = blockIdx.z;
    int base = (b * SEQB + c * CL) * DDIM + d;
    float h = g_Hin[(b * NC + c) * DDIM + d];
#pragma unroll 4
    for (int i = 0; i < CL; i++) {
        int o = base + i * DDIM;
        float a = g_a[o];
        float x = g_nx[o];
        h = fmaf(a, h, x);
        g_nx[o] = h * g_yb[o];   // h * y_branch, feeds final GEMM
    }
}

// ---------------- launcher ----------------
extern "C" void kernel_launch(void* const* d_in, const int* in_sizes, int n_in,
                              void* d_out, int out_size) {
    const float* x_in    = (const float*)d_in[0];
    const int*   pos     = (const int*)d_in[1];
    const float* prev_h  = (const float*)d_in[2];
    const float* w_y     = (const float*)d_in[3];
    const float* b_y     = (const float*)d_in[4];
    const float* w_x     = (const float*)d_in[5];
    const float* b_x     = (const float*)d_in[6];
    const float* w_out   = (const float*)d_in[7];
    const float* b_out   = (const float*)d_in[8];
    const float* conv_w  = (const float*)d_in[9];
    const float* conv_b  = (const float*)d_in[10];
    const float* a_param = (const float*)d_in[11];
    const float* ig_w    = (const float*)d_in[12];
    const float* ig_b    = (const float*)d_in[13];
    const float* ag_w    = (const float*)d_in[14];
    const float* ag_b    = (const float*)d_in[15];
    float* out = (float*)d_out;

    float *p_xb, *p_yb, *p_nx;
    cudaGetSymbolAddress((void**)&p_xb, g_xb);
    cudaGetSymbolAddress((void**)&p_yb, g_yb);
    cudaGetSymbolAddress((void**)&p_nx, g_nx);

    reset_kernel<<<(TOK + 255) / 256, 256>>>(pos);

    dim3 gg(DDIM / 128, TOK / 128);
    sgemm128<<<gg, 256>>>(x_in, w_x, b_x, p_xb, 0);
    sgemm128<<<gg, 256>>>(x_in, w_y, b_y, p_yb, 1);

    conv_kernel<<<(TOK * DDIM + 255) / 256, 256>>>(conv_w, conv_b);

    dim3 gt(BW / 64, TOK / 128, HEADS);
    gates_kernel<<<gt, 256>>>(ig_w, ig_b, ag_w, ag_b, a_param);

    scan_phase1<<<dim3(DDIM / 256, NC, 2), 256>>>();
    scan_phase2<<<(2 * DDIM + 255) / 256, 256>>>(prev_h);
    scan_phase3<<<dim3(DDIM / 256, NC, 2), 256>>>();

    sgemm128<<<gg, 256>>>(p_nx, w_out, b_out, out, 0);
}

// round 4
// speedup vs baseline: 2.6751x; 2.6751x over previous
#include <cuda_runtime.h>
#include <math.h>
#include <stdint.h>

#define TOK 8192
#define SEQB 4096
#define DDIM 2560
#define HEADS 10
#define BW 256
#define NC 32
#define CL 128

// ---------------- scratch (static device globals; no allocation) ----------------
__device__ float g_xb[(size_t)TOK * DDIM];   // x-branch (pre-conv)
__device__ float g_yb[(size_t)TOK * DDIM];   // gelu(y-branch)
__device__ float g_co[(size_t)TOK * DDIM];   // conv output
__device__ float g_a [(size_t)TOK * DDIM];   // recurrence decay a_t
__device__ float g_nx[(size_t)TOK * DDIM];   // normalized x; later h*y
__device__ float g_Aag[2 * NC * DDIM];
__device__ float g_Hag[2 * NC * DDIM];
__device__ float g_Hin[2 * NC * DDIM];
__device__ unsigned char g_reset[TOK];

// ---------------- math helpers ----------------
__device__ __forceinline__ float gelu_tanh(float x) {
    float x3 = x * x * x;
    float t = tanhf(0.7978845608028654f * (x + 0.044715f * x3));
    return 0.5f * x * (1.0f + t);
}
__device__ __forceinline__ float sigmoidf(float x) {
    return 1.0f / (1.0f + expf(-x));
}
__device__ __forceinline__ float softplusf(float x) {
    return (x > 20.0f) ? x : log1pf(expf(x));
}

// ---------------- async-copy / mma helpers (sm_80+ features only) ----------------
__device__ __forceinline__ uint32_t smem_u32(const void* p) {
    uint32_t a;
    asm("{ .reg .u64 t; cvta.to.shared.u64 t, %1; cvt.u32.u64 %0, t; }" : "=r"(a) : "l"(p));
    return a;
}
__device__ __forceinline__ void cp16(uint32_t dst, const void* src) {
    asm volatile("cp.async.ca.shared.global [%0], [%1], 16;" :: "r"(dst), "l"(src));
}
__device__ __forceinline__ void cp_commit() {
    asm volatile("cp.async.commit_group;" ::: "memory");
}
template <int N> __device__ __forceinline__ void cp_wait() {
    asm volatile("cp.async.wait_group %0;" :: "n"(N) : "memory");
}
__device__ __forceinline__ uint32_t f2tf32(float x) {
    uint32_t u;
    asm("cvt.rna.tf32.f32 %0, %1;" : "=r"(u) : "f"(x));
    return u;
}
__device__ __forceinline__ void mma_tf32(float* c, const uint32_t* a, const uint32_t* b) {
    asm volatile(
        "mma.sync.aligned.m16n8k8.row.col.f32.tf32.tf32.f32 "
        "{%0,%1,%2,%3}, {%4,%5,%6,%7}, {%8,%9}, {%0,%1,%2,%3};"
        : "+f"(c[0]), "+f"(c[1]), "+f"(c[2]), "+f"(c[3])
        : "r"(a[0]), "r"(a[1]), "r"(a[2]), "r"(a[3]), "r"(b[0]), "r"(b[1]));
}

// swizzled smem word index for a [128 x 32] fp32 tile (conflict-free fragments)
__device__ __forceinline__ int swz(int r, int c) {
    return r * 32 + ((((c >> 2) ^ r) & 7) << 2) + (c & 3);
}

// ---------------- reset-mask kernel (handles int32 or int64 position_ids) ----------------
__global__ void reset_kernel(const int* __restrict__ pos32) {
    int m = blockIdx.x * 256 + threadIdx.x;
    if (m >= TOK) return;
    bool is64 = (pos32[1] == 0 && pos32[2] == 1);
    bool r;
    if (is64) r = (pos32[2 * m] == 0 && pos32[2 * m + 1] == 0);
    else      r = (pos32[m] == 0);
    g_reset[m] = r ? 1 : 0;
}

// =======================================================================
// tf32 mma.sync GEMM: C[m,n] = sum_k A[m,k]*W[n,k] + bias[n] (opt. gelu)
// CTA tile 128x128, K-chunk 32, 3-stage cp.async pipeline, 8 warps (4x2)
// =======================================================================
#define GSTG 3
#define GNK (DDIM / 32)   // 80
#define GSMEM (GSTG * 2 * 4096 * 4)  // 98304 bytes

__global__ __launch_bounds__(256, 2) void gemm_tf32(
    const float* __restrict__ A,
    const float* __restrict__ W,
    const float* __restrict__ bias,
    float* __restrict__ C,
    int do_gelu)
{
    extern __shared__ __align__(16) float sm[];
    float* As = sm;                  // [GSTG][4096]
    float* Bs = sm + GSTG * 4096;    // [GSTG][4096]
    const uint32_t sa = smem_u32(As);
    const uint32_t sbb = smem_u32(Bs);

    const int tid = threadIdx.x;
    const int lane = tid & 31;
    const int wid = tid >> 5;
    const int wm = wid & 3;          // 0..3  -> 32-row slice
    const int wn = wid >> 2;         // 0..1  -> 64-col slice
    const int m0 = blockIdx.y * 128;
    const int n0 = blockIdx.x * 128;

    // per-thread global-load coordinates (4 float4s per tile per stage)
    const int lrow = tid >> 3;       // base row for i=0 (stride 32 rows per i)
    const int lc4 = tid & 7;
    const int lsw = ((lc4 ^ (lrow & 7)) << 2) + lrow * 32;  // swizzled word offset

    float acc[2][8][4];
#pragma unroll
    for (int i = 0; i < 2; i++)
#pragma unroll
        for (int j = 0; j < 8; j++)
#pragma unroll
            for (int q = 0; q < 4; q++) acc[i][j][q] = 0.0f;

#define LOAD_STAGE(s, kc)                                                        \
    {                                                                            \
        int k0 = (kc) * 32;                                                      \
        _Pragma("unroll")                                                        \
        for (int i = 0; i < 4; i++) {                                            \
            int row = lrow + i * 32;                                             \
            int sw = lsw + i * 32 * 32;                                          \
            cp16(sa  + ((s) * 4096 + sw) * 4,                                    \
                 A + (size_t)(m0 + row) * DDIM + k0 + lc4 * 4);                  \
            cp16(sbb + ((s) * 4096 + sw) * 4,                                    \
                 W + (size_t)(n0 + row) * DDIM + k0 + lc4 * 4);                  \
        }                                                                        \
        cp_commit();                                                             \
    }

    LOAD_STAGE(0, 0);
    LOAD_STAGE(1, 1);

    const int ar0 = wm * 32 + (lane >> 2);
    const int ac0 = lane & 3;
    const int bn0 = wn * 64 + (lane >> 2);

    for (int kc = 0; kc < GNK; kc++) {
        cp_wait<1>();
        __syncthreads();
        int nxt = kc + GSTG - 1;
        if (nxt < GNK) {
            LOAD_STAGE(nxt % GSTG, nxt);
        } else {
            cp_commit();
        }
        const float* a_s = As + (kc % GSTG) * 4096;
        const float* b_s = Bs + (kc % GSTG) * 4096;
#pragma unroll
        for (int ks = 0; ks < 4; ks++) {
            const int k = ks * 8;
            uint32_t af[2][4];
#pragma unroll
            for (int i = 0; i < 2; i++) {
                int r = ar0 + i * 16;
                af[i][0] = f2tf32(a_s[swz(r,     k + ac0)]);
                af[i][1] = f2tf32(a_s[swz(r + 8, k + ac0)]);
                af[i][2] = f2tf32(a_s[swz(r,     k + ac0 + 4)]);
                af[i][3] = f2tf32(a_s[swz(r + 8, k + ac0 + 4)]);
            }
            uint32_t bf[8][2];
#pragma unroll
            for (int j = 0; j < 8; j++) {
                int n = bn0 + j * 8;
                bf[j][0] = f2tf32(b_s[swz(n, k + ac0)]);
                bf[j][1] = f2tf32(b_s[swz(n, k + ac0 + 4)]);
            }
#pragma unroll
            for (int i = 0; i < 2; i++)
#pragma unroll
                for (int j = 0; j < 8; j++)
                    mma_tf32(acc[i][j], af[i], bf[j]);
        }
        __syncthreads();
    }

    // epilogue
#pragma unroll
    for (int i = 0; i < 2; i++) {
        int r = m0 + wm * 32 + i * 16 + (lane >> 2);
#pragma unroll
        for (int j = 0; j < 8; j++) {
            int col = n0 + wn * 64 + j * 8 + 2 * (lane & 3);
            float b0 = bias[col], b1 = bias[col + 1];
            float2 v0 = make_float2(acc[i][j][0] + b0, acc[i][j][1] + b1);
            float2 v1 = make_float2(acc[i][j][2] + b0, acc[i][j][3] + b1);
            if (do_gelu) {
                v0.x = gelu_tanh(v0.x); v0.y = gelu_tanh(v0.y);
                v1.x = gelu_tanh(v1.x); v1.y = gelu_tanh(v1.y);
            }
            *(float2*)(C + (size_t)r * DDIM + col) = v0;
            *(float2*)(C + (size_t)(r + 8) * DDIM + col) = v1;
        }
    }
}

// ---------------- depthwise causal conv (width 4), float4 vectorized ----------------
__global__ __launch_bounds__(256) void conv_kernel(const float* __restrict__ cw,
                                                   const float* __restrict__ cb) {
    const int D4 = DDIM / 4;
    int idx = blockIdx.x * 256 + threadIdx.x;
    if (idx >= TOK * D4) return;
    int d4 = idx % D4, m = idx / D4;
    int t = m & (SEQB - 1);
    int d0 = d4 * 4;
    const float4* X = (const float4*)g_xb;
    float4 acc = make_float4(cb[d0], cb[d0 + 1], cb[d0 + 2], cb[d0 + 3]);
    float4 x0 = X[idx];
    acc.x = fmaf(x0.x, cw[(d0 + 0) * 4 + 3], acc.x);
    acc.y = fmaf(x0.y, cw[(d0 + 1) * 4 + 3], acc.y);
    acc.z = fmaf(x0.z, cw[(d0 + 2) * 4 + 3], acc.z);
    acc.w = fmaf(x0.w, cw[(d0 + 3) * 4 + 3], acc.w);
    if (t >= 1) {
        float4 x1 = X[idx - D4];
        acc.x = fmaf(x1.x, cw[(d0 + 0) * 4 + 2], acc.x);
        acc.y = fmaf(x1.y, cw[(d0 + 1) * 4 + 2], acc.y);
        acc.z = fmaf(x1.z, cw[(d0 + 2) * 4 + 2], acc.z);
        acc.w = fmaf(x1.w, cw[(d0 + 3) * 4 + 2], acc.w);
    }
    if (t >= 2) {
        float4 x2 = X[idx - 2 * D4];
        acc.x = fmaf(x2.x, cw[(d0 + 0) * 4 + 1], acc.x);
        acc.y = fmaf(x2.y, cw[(d0 + 1) * 4 + 1], acc.y);
        acc.z = fmaf(x2.z, cw[(d0 + 2) * 4 + 1], acc.z);
        acc.w = fmaf(x2.w, cw[(d0 + 3) * 4 + 1], acc.w);
    }
    if (t >= 3) {
        float4 x3 = X[idx - 3 * D4];
        acc.x = fmaf(x3.x, cw[(d0 + 0) * 4 + 0], acc.x);
        acc.y = fmaf(x3.y, cw[(d0 + 1) * 4 + 0], acc.y);
        acc.z = fmaf(x3.z, cw[(d0 + 2) * 4 + 0], acc.z);
        acc.w = fmaf(x3.w, cw[(d0 + 3) * 4 + 0], acc.w);
    }
    ((float4*)g_co)[idx] = acc;
}

// ---------------- block-diagonal gates + RG-LRU pointwise (SIMT) ----------------
__global__ __launch_bounds__(256) void gates_kernel(const float* __restrict__ ig_w,
                                                    const float* __restrict__ ig_b,
                                                    const float* __restrict__ ag_w,
                                                    const float* __restrict__ ag_b,
                                                    const float* __restrict__ a_param) {
    __shared__ float Xs[16][128];
    __shared__ float Wxs[16][64];
    __shared__ float Was[16][64];
    const int tid = threadIdx.x;
    const int j0 = blockIdx.x * 64;
    const int m0 = blockIdx.y * 128;
    const int h  = blockIdx.z;
    const int ty = tid >> 4;
    const int tx = tid & 15;

    float gx[8][4], ga[8][4];
#pragma unroll
    for (int i = 0; i < 8; i++)
#pragma unroll
        for (int j = 0; j < 4; j++) { gx[i][j] = 0.0f; ga[i][j] = 0.0f; }

    const int xrow = tid >> 1;
    const int xk   = (tid & 1) * 8;
    const float* Xp = g_co + (size_t)(m0 + xrow) * DDIM + h * BW + xk;
    const int wrow = (tid & 127) >> 1;
    const int wk   = (tid & 1) * 8;
    const float* Wg = (tid < 128) ? (ig_w + (size_t)h * 65536 + (size_t)(j0 + wrow) * 256 + wk)
                                  : (ag_w + (size_t)h * 65536 + (size_t)(j0 + wrow) * 256 + wk);

    for (int k0 = 0; k0 < BW; k0 += 16) {
        float4 x0 = *(const float4*)(Xp + k0);
        float4 x1 = *(const float4*)(Xp + k0 + 4);
        float4 w0 = *(const float4*)(Wg + k0);
        float4 w1 = *(const float4*)(Wg + k0 + 4);
        __syncthreads();
        Xs[xk + 0][xrow] = x0.x; Xs[xk + 1][xrow] = x0.y;
        Xs[xk + 2][xrow] = x0.z; Xs[xk + 3][xrow] = x0.w;
        Xs[xk + 4][xrow] = x1.x; Xs[xk + 5][xrow] = x1.y;
        Xs[xk + 6][xrow] = x1.z; Xs[xk + 7][xrow] = x1.w;
        if (tid < 128) {
            Wxs[wk + 0][wrow] = w0.x; Wxs[wk + 1][wrow] = w0.y;
            Wxs[wk + 2][wrow] = w0.z; Wxs[wk + 3][wrow] = w0.w;
            Wxs[wk + 4][wrow] = w1.x; Wxs[wk + 5][wrow] = w1.y;
            Wxs[wk + 6][wrow] = w1.z; Wxs[wk + 7][wrow] = w1.w;
        } else {
            Was[wk + 0][wrow] = w0.x; Was[wk + 1][wrow] = w0.y;
            Was[wk + 2][wrow] = w0.z; Was[wk + 3][wrow] = w0.w;
            Was[wk + 4][wrow] = w1.x; Was[wk + 5][wrow] = w1.y;
            Was[wk + 6][wrow] = w1.z; Was[wk + 7][wrow] = w1.w;
        }
        __syncthreads();
#pragma unroll
        for (int k = 0; k < 16; k++) {
            float af[8], bx[4], ba[4];
            *(float4*)&af[0] = *(const float4*)&Xs[k][ty * 8];
            *(float4*)&af[4] = *(const float4*)&Xs[k][ty * 8 + 4];
            *(float4*)&bx[0] = *(const float4*)&Wxs[k][tx * 4];
            *(float4*)&ba[0] = *(const float4*)&Was[k][tx * 4];
#pragma unroll
            for (int i = 0; i < 8; i++)
#pragma unroll
                for (int j = 0; j < 4; j++) {
                    gx[i][j] = fmaf(af[i], bx[j], gx[i][j]);
                    ga[i][j] = fmaf(af[i], ba[j], ga[i][j]);
                }
        }
    }

#pragma unroll
    for (int i = 0; i < 8; i++) {
        int m = m0 + ty * 8 + i;
        bool r = (g_reset[m] != 0);
#pragma unroll
        for (int jj = 0; jj < 4; jj++) {
            int j = j0 + tx * 4 + jj;
            int d = h * BW + j;
            float gxs = sigmoidf(gx[i][jj] + ig_b[j]);
            float gas = sigmoidf(ga[i][jj] + ag_b[j]);
            float log_a = -8.0f * gas * softplusf(a_param[d]);
            float a = expf(log_a);
            float mult = r ? 1.0f : sqrtf(fmaxf(1.0f - expf(2.0f * log_a), 0.0f));
            size_t o = (size_t)m * DDIM + d;
            float co = g_co[o];
            g_nx[o] = co * gxs * mult;
            g_a[o]  = r ? 0.0f : a;
        }
    }
}

// ---------------- chunked linear scan ----------------
__global__ __launch_bounds__(256) void scan_phase1() {
    int d = blockIdx.x * 256 + threadIdx.x;
    int c = blockIdx.y;
    int b = blockIdx.z;
    int base = (b * SEQB + c * CL) * DDIM + d;
    float A = 1.0f, H = 0.0f;
#pragma unroll 4
    for (int i = 0; i < CL; i++) {
        float a = g_a[base + i * DDIM];
        float x = g_nx[base + i * DDIM];
        H = fmaf(a, H, x);
        A *= a;
    }
    int o = (b * NC + c) * DDIM + d;
    g_Aag[o] = A;
    g_Hag[o] = H;
}

__global__ __launch_bounds__(256) void scan_phase2(const float* __restrict__ prev_h) {
    int t = blockIdx.x * 256 + threadIdx.x;
    if (t >= 2 * DDIM) return;
    int b = t / DDIM, d = t % DDIM;
    float h = prev_h[t];
#pragma unroll
    for (int c = 0; c < NC; c++) {
        int o = (b * NC + c) * DDIM + d;
        g_Hin[o] = h;
        h = fmaf(g_Aag[o], h, g_Hag[o]);
    }
}

__global__ __launch_bounds__(256) void scan_phase3() {
    int d = blockIdx.x * 256 + threadIdx.x;
    int c = blockIdx.y;
    int b = blockIdx.z;
    int base = (b * SEQB + c * CL) * DDIM + d;
    float h = g_Hin[(b * NC + c) * DDIM + d];
#pragma unroll 4
    for (int i = 0; i < CL; i++) {
        int o = base + i * DDIM;
        float a = g_a[o];
        float x = g_nx[o];
        h = fmaf(a, h, x);
        g_nx[o] = h * g_yb[o];   // h * y_branch, feeds final GEMM
    }
}

// ---------------- launcher ----------------
extern "C" void kernel_launch(void* const* d_in, const int* in_sizes, int n_in,
                              void* d_out, int out_size) {
    const float* x_in    = (const float*)d_in[0];
    const int*   pos     = (const int*)d_in[1];
    const float* prev_h  = (const float*)d_in[2];
    const float* w_y     = (const float*)d_in[3];
    const float* b_y     = (const float*)d_in[4];
    const float* w_x     = (const float*)d_in[5];
    const float* b_x     = (const float*)d_in[6];
    const float* w_out   = (const float*)d_in[7];
    const float* b_out   = (const float*)d_in[8];
    const float* conv_w  = (const float*)d_in[9];
    const float* conv_b  = (const float*)d_in[10];
    const float* a_param = (const float*)d_in[11];
    const float* ig_w    = (const float*)d_in[12];
    const float* ig_b    = (const float*)d_in[13];
    const float* ag_w    = (const float*)d_in[14];
    const float* ag_b    = (const float*)d_in[15];
    float* out = (float*)d_out;

    float *p_xb, *p_yb, *p_nx;
    cudaGetSymbolAddress((void**)&p_xb, g_xb);
    cudaGetSymbolAddress((void**)&p_yb, g_yb);
    cudaGetSymbolAddress((void**)&p_nx, g_nx);

    cudaFuncSetAttribute(gemm_tf32, cudaFuncAttributeMaxDynamicSharedMemorySize, GSMEM);

    reset_kernel<<<(TOK + 255) / 256, 256>>>(pos);

    dim3 gg(DDIM / 128, TOK / 128);  // (20, 64)
    gemm_tf32<<<gg, 256, GSMEM>>>(x_in, w_x, b_x, p_xb, 0);
    gemm_tf32<<<gg, 256, GSMEM>>>(x_in, w_y, b_y, p_yb, 1);

    conv_kernel<<<(TOK * (DDIM / 4) + 255) / 256, 256>>>(conv_w, conv_b);

    dim3 gt(BW / 64, TOK / 128, HEADS);
    gates_kernel<<<gt, 256>>>(ig_w, ig_b, ag_w, ag_b, a_param);

    scan_phase1<<<dim3(DDIM / 256, NC, 2), 256>>>();
    scan_phase2<<<(2 * DDIM + 255) / 256, 256>>>(prev_h);
    scan_phase3<<<dim3(DDIM / 256, NC, 2), 256>>>();

    gemm_tf32<<<gg, 256, GSMEM>>>(p_nx, w_out, b_out, out, 0);
}

// round 5
// speedup vs baseline: 5.5085x; 2.0592x over previous
#include <cuda_runtime.h>
#include <cuda_fp16.h>
#include <math.h>
#include <stdint.h>

#define TOK 8192
#define SEQB 4096
#define DDIM 2560
#define HEADS 10
#define BW 256
#define NC 32
#define CL 128
#define NGATE 5120   // ig rows (2560) ++ ag rows (2560)

// ---------------- scratch (static device globals; no allocation) ----------------
__device__ float  g_xb[(size_t)TOK * DDIM];    // x-branch (pre-conv) fp32
__device__ float  g_yb[(size_t)TOK * DDIM];    // gelu(y-branch) fp32
__device__ float  g_co[(size_t)TOK * DDIM];    // conv output fp32
__device__ float  g_a [(size_t)TOK * DDIM];    // recurrence decay a_t
__device__ float  g_nx[(size_t)TOK * DDIM];    // normalized x (scan input)
__device__ float  g_gl[(size_t)TOK * NGATE];   // gate logits (ig | ag)
__device__ __half g_xh [(size_t)TOK * DDIM];   // X in half
__device__ __half g_coh[(size_t)TOK * DDIM];   // conv out in half
__device__ __half g_nxh[(size_t)TOK * DDIM];   // h*y in half (final GEMM input)
__device__ __half g_wxh[DDIM * DDIM];
__device__ __half g_wyh[DDIM * DDIM];
__device__ __half g_woh[DDIM * DDIM];
__device__ __half g_gwh[(size_t)NGATE * BW];   // [ig rows ; ag rows] x 256, K-major
__device__ float  g_Aag[2 * NC * DDIM];
__device__ float  g_Hag[2 * NC * DDIM];
__device__ float  g_Hin[2 * NC * DDIM];
__device__ unsigned char g_reset[TOK];

// ---------------- math helpers ----------------
__device__ __forceinline__ float gelu_tanh(float x) {
    float x3 = x * x * x;
    float t = tanhf(0.7978845608028654f * (x + 0.044715f * x3));
    return 0.5f * x * (1.0f + t);
}
__device__ __forceinline__ float sigmoidf(float x) {
    return 1.0f / (1.0f + expf(-x));
}
__device__ __forceinline__ float softplusf(float x) {
    return (x > 20.0f) ? x : log1pf(expf(x));
}

// ---------------- async-copy / mma helpers (sm_80+ features only) ----------------
__device__ __forceinline__ uint32_t smem_u32(const void* p) {
    uint32_t a;
    asm("{ .reg .u64 t; cvta.to.shared.u64 t, %1; cvt.u32.u64 %0, t; }" : "=r"(a) : "l"(p));
    return a;
}
__device__ __forceinline__ void cp16(uint32_t dst, const void* src) {
    asm volatile("cp.async.ca.shared.global [%0], [%1], 16;" :: "r"(dst), "l"(src));
}
__device__ __forceinline__ void cp_commit() {
    asm volatile("cp.async.commit_group;" ::: "memory");
}
template <int N> __device__ __forceinline__ void cp_wait() {
    asm volatile("cp.async.wait_group %0;" :: "n"(N) : "memory");
}
__device__ __forceinline__ void mma_f16(float* c, const uint32_t* a, const uint32_t* b) {
    asm volatile(
        "mma.sync.aligned.m16n8k16.row.col.f32.f16.f16.f32 "
        "{%0,%1,%2,%3}, {%4,%5,%6,%7}, {%8,%9}, {%0,%1,%2,%3};"
        : "+f"(c[0]), "+f"(c[1]), "+f"(c[2]), "+f"(c[3])
        : "r"(a[0]), "r"(a[1]), "r"(a[2]), "r"(a[3]), "r"(b[0]), "r"(b[1]));
}
// byte offset of half element (r, kh) inside a [128 x 64-half] SW128-swizzled tile
__device__ __forceinline__ int soff(int r, int kh) {
    return r * 128 + ((((kh >> 3) ^ r) & 7) << 4) + ((kh & 7) << 1);
}

// ---------------- reset-mask kernel (handles int32 or int64 position_ids) ----------------
__global__ void reset_kernel(const int* __restrict__ pos32) {
    int m = blockIdx.x * 256 + threadIdx.x;
    if (m >= TOK) return;
    bool is64 = (pos32[1] == 0 && pos32[2] == 1);
    bool r;
    if (is64) r = (pos32[2 * m] == 0 && pos32[2 * m + 1] == 0);
    else      r = (pos32[m] == 0);
    g_reset[m] = r ? 1 : 0;
}

// ---------------- fp32 -> fp16 conversion ----------------
__global__ void f2h_kernel(const float* __restrict__ src, __half* __restrict__ dst, int n4) {
    int i = blockIdx.x * 256 + threadIdx.x;
    if (i >= n4) return;
    float4 v = ((const float4*)src)[i];
    __half2 h0 = __floats2half2_rn(v.x, v.y);
    __half2 h1 = __floats2half2_rn(v.z, v.w);
    ((__half2*)dst)[2 * i]     = h0;
    ((__half2*)dst)[2 * i + 1] = h1;
}

// =======================================================================
// fp16 mma.sync GEMM: C[m,n] = sum_k A[m,k]*W[n,k] (+ bias, opt. gelu)
// CTA tile 128x128, K-chunk 64 halves, 3-stage cp.async, 8 warps (4x2)
// gates_mode: A column window = head(n)*256, no bias, K=256
// =======================================================================
#define GSMEM (3 * 32768)   // 96 KB

__global__ __launch_bounds__(256, 2) void gemm_f16(
    const __half* __restrict__ A,
    const __half* __restrict__ W,
    const float* __restrict__ bias,
    float* __restrict__ C,
    int K, int ldW, int ldc, int gates_mode, int do_gelu)
{
    extern __shared__ __align__(16) char smem[];
    const uint32_t sbase = smem_u32(smem);

    const int tid = threadIdx.x;
    const int lane = tid & 31;
    const int wid = tid >> 5;
    const int wm = wid & 3;
    const int wn = wid >> 2;
    const int m0 = blockIdx.y * 128;
    const int n0 = blockIdx.x * 128;
    const int aoff = gates_mode ? (((n0 % 2560) >> 8) << 8) : 0;
    const int NKC = K >> 6;

    const int lrow = tid >> 3;     // 0..31, +32*i
    const int chk  = tid & 7;      // 16B chunk within 128B row

    float acc[2][8][4];
#pragma unroll
    for (int i = 0; i < 2; i++)
#pragma unroll
        for (int j = 0; j < 8; j++)
#pragma unroll
            for (int q = 0; q < 4; q++) acc[i][j][q] = 0.0f;

#define LD_STAGE(s, kc)                                                           \
    {                                                                             \
        int ka = aoff + (kc) * 64 + chk * 8;                                      \
        int kb = (kc) * 64 + chk * 8;                                             \
        _Pragma("unroll")                                                         \
        for (int i = 0; i < 4; i++) {                                             \
            int row = lrow + i * 32;                                              \
            int sw = row * 128 + (((chk ^ row) & 7) << 4);                        \
            cp16(sbase + (s) * 32768 + sw,                                        \
                 A + (size_t)(m0 + row) * DDIM + ka);                             \
            cp16(sbase + (s) * 32768 + 16384 + sw,                                \
                 W + (size_t)(n0 + row) * ldW + kb);                              \
        }                                                                         \
        cp_commit();                                                              \
    }

    LD_STAGE(0, 0);
    LD_STAGE(1, 1);

    const int g = lane >> 2;
    const int t2 = (lane & 3) * 2;

    for (int kc = 0; kc < NKC; kc++) {
        cp_wait<1>();
        __syncthreads();
        int nxt = kc + 2;
        if (nxt < NKC) {
            LD_STAGE(nxt % 3, nxt);
        } else {
            cp_commit();
        }
        const char* As = smem + (kc % 3) * 32768;
        const char* Bs = As + 16384;
#pragma unroll
        for (int ks = 0; ks < 4; ks++) {
            const int kh = ks * 16 + t2;
            uint32_t af[2][4];
#pragma unroll
            for (int i = 0; i < 2; i++) {
                int r = wm * 32 + i * 16 + g;
                af[i][0] = *(const uint32_t*)(As + soff(r,     kh));
                af[i][1] = *(const uint32_t*)(As + soff(r + 8, kh));
                af[i][2] = *(const uint32_t*)(As + soff(r,     kh + 8));
                af[i][3] = *(const uint32_t*)(As + soff(r + 8, kh + 8));
            }
            uint32_t bf[8][2];
#pragma unroll
            for (int j = 0; j < 8; j++) {
                int n = wn * 64 + j * 8 + g;
                bf[j][0] = *(const uint32_t*)(Bs + soff(n, kh));
                bf[j][1] = *(const uint32_t*)(Bs + soff(n, kh + 8));
            }
#pragma unroll
            for (int i = 0; i < 2; i++)
#pragma unroll
                for (int j = 0; j < 8; j++)
                    mma_f16(acc[i][j], af[i], bf[j]);
        }
        __syncthreads();
    }

    // epilogue
#pragma unroll
    for (int i = 0; i < 2; i++) {
        int r = m0 + wm * 32 + i * 16 + g;
#pragma unroll
        for (int j = 0; j < 8; j++) {
            int col = n0 + wn * 64 + j * 8 + t2;
            float b0 = 0.0f, b1 = 0.0f;
            if (bias) { b0 = bias[col]; b1 = bias[col + 1]; }
            float2 v0 = make_float2(acc[i][j][0] + b0, acc[i][j][1] + b1);
            float2 v1 = make_float2(acc[i][j][2] + b0, acc[i][j][3] + b1);
            if (do_gelu) {
                v0.x = gelu_tanh(v0.x); v0.y = gelu_tanh(v0.y);
                v1.x = gelu_tanh(v1.x); v1.y = gelu_tanh(v1.y);
            }
            *(float2*)(C + (size_t)r * ldc + col) = v0;
            *(float2*)(C + (size_t)(r + 8) * ldc + col) = v1;
        }
    }
}

// ---------------- depthwise causal conv: 4 timesteps per thread ----------------
// writes fp32 g_co (pointwise input) and fp16 g_coh (gates GEMM input)
__global__ __launch_bounds__(256) void conv_kernel(const float* __restrict__ cw,
                                                   const float* __restrict__ cb) {
    const int D4 = DDIM / 4;             // 640
    const int TB = SEQB / 4;             // 1024
    int idx = blockIdx.x * 256 + threadIdx.x;
    if (idx >= 2 * TB * D4) return;
    int d4 = idx % D4;
    int tb = (idx / D4) % TB;
    int b  = idx / (D4 * TB);
    int t0 = tb * 4;
    int d0 = d4 * 4;

    float cwv[4][4];
#pragma unroll
    for (int e = 0; e < 4; e++)
#pragma unroll
        for (int k = 0; k < 4; k++) cwv[e][k] = cw[(d0 + e) * 4 + k];
    float4 cb4 = *(const float4*)(cb + d0);

    const float4* X = (const float4*)g_xb;
    float4 xv[7];
#pragma unroll
    for (int i = 0; i < 7; i++) {
        int t = t0 + i - 3;
        if (t >= 0) xv[i] = X[((size_t)(b * SEQB + t)) * D4 + d4];
        else        xv[i] = make_float4(0.f, 0.f, 0.f, 0.f);
    }

#pragma unroll
    for (int jj = 0; jj < 4; jj++) {
        float4 acc = cb4;
#pragma unroll
        for (int k = 0; k < 4; k++) {
            acc.x = fmaf(xv[jj + k].x, cwv[0][k], acc.x);
            acc.y = fmaf(xv[jj + k].y, cwv[1][k], acc.y);
            acc.z = fmaf(xv[jj + k].z, cwv[2][k], acc.z);
            acc.w = fmaf(xv[jj + k].w, cwv[3][k], acc.w);
        }
        size_t o = ((size_t)(b * SEQB + t0 + jj)) * D4 + d4;
        ((float4*)g_co)[o] = acc;
        __half2 h0 = __floats2half2_rn(acc.x, acc.y);
        __half2 h1 = __floats2half2_rn(acc.z, acc.w);
        ((__half2*)g_coh)[2 * o]     = h0;
        ((__half2*)g_coh)[2 * o + 1] = h1;
    }
}

// ---------------- RG-LRU pointwise (from gate logits) ----------------
__global__ __launch_bounds__(256) void rglru_pw(const float* __restrict__ ig_b,
                                                const float* __restrict__ ag_b,
                                                const float* __restrict__ a_param) {
    const int D4 = DDIM / 4;
    int idx = blockIdx.x * 256 + threadIdx.x;
    if (idx >= TOK * D4) return;
    int d4 = idx % D4, m = idx / D4;
    int d0 = d4 * 4;
    int j0 = d0 & 255;
    bool rs = (g_reset[m] != 0);

    float4 li = *(const float4*)(g_gl + (size_t)m * NGATE + d0);
    float4 la = *(const float4*)(g_gl + (size_t)m * NGATE + 2560 + d0);
    float4 co = ((const float4*)g_co)[idx];
    float4 bi = *(const float4*)(ig_b + j0);
    float4 ba = *(const float4*)(ag_b + j0);
    float4 ap = *(const float4*)(a_param + d0);

    float liv[4] = {li.x, li.y, li.z, li.w};
    float lav[4] = {la.x, la.y, la.z, la.w};
    float cov[4] = {co.x, co.y, co.z, co.w};
    float biv[4] = {bi.x, bi.y, bi.z, bi.w};
    float bav[4] = {ba.x, ba.y, ba.z, ba.w};
    float apv[4] = {ap.x, ap.y, ap.z, ap.w};
    float nxv[4], av[4];
#pragma unroll
    for (int e = 0; e < 4; e++) {
        float gx = sigmoidf(liv[e] + biv[e]);
        float ga = sigmoidf(lav[e] + bav[e]);
        float log_a = -8.0f * ga * softplusf(apv[e]);
        float a = expf(log_a);
        float mult = rs ? 1.0f : sqrtf(fmaxf(1.0f - expf(2.0f * log_a), 0.0f));
        nxv[e] = cov[e] * gx * mult;
        av[e]  = rs ? 0.0f : a;
    }
    ((float4*)g_nx)[idx] = make_float4(nxv[0], nxv[1], nxv[2], nxv[3]);
    ((float4*)g_a)[idx]  = make_float4(av[0], av[1], av[2], av[3]);
}

// ---------------- chunked linear scan ----------------
__global__ __launch_bounds__(256) void scan_phase1() {
    int d = blockIdx.x * 256 + threadIdx.x;
    int c = blockIdx.y;
    int b = blockIdx.z;
    int base = (b * SEQB + c * CL) * DDIM + d;
    float A = 1.0f, H = 0.0f;
#pragma unroll 4
    for (int i = 0; i < CL; i++) {
        float a = g_a[base + i * DDIM];
        float x = g_nx[base + i * DDIM];
        H = fmaf(a, H, x);
        A *= a;
    }
    int o = (b * NC + c) * DDIM + d;
    g_Aag[o] = A;
    g_Hag[o] = H;
}

__global__ __launch_bounds__(256) void scan_phase2(const float* __restrict__ prev_h) {
    int t = blockIdx.x * 256 + threadIdx.x;
    if (t >= 2 * DDIM) return;
    int b = t / DDIM, d = t % DDIM;
    float h = prev_h[t];
#pragma unroll
    for (int c = 0; c < NC; c++) {
        int o = (b * NC + c) * DDIM + d;
        g_Hin[o] = h;
        h = fmaf(g_Aag[o], h, g_Hag[o]);
    }
}

__global__ __launch_bounds__(256) void scan_phase3() {
    int d = blockIdx.x * 256 + threadIdx.x;
    int c = blockIdx.y;
    int b = blockIdx.z;
    int base = (b * SEQB + c * CL) * DDIM + d;
    float h = g_Hin[(b * NC + c) * DDIM + d];
#pragma unroll 4
    for (int i = 0; i < CL; i++) {
        int o = base + i * DDIM;
        float a = g_a[o];
        float x = g_nx[o];
        h = fmaf(a, h, x);
        g_nxh[o] = __float2half(h * g_yb[o]);   // h * y_branch -> final GEMM (fp16)
    }
}

// ---------------- launcher ----------------
extern "C" void kernel_launch(void* const* d_in, const int* in_sizes, int n_in,
                              void* d_out, int out_size) {
    const float* x_in    = (const float*)d_in[0];
    const int*   pos     = (const int*)d_in[1];
    const float* prev_h  = (const float*)d_in[2];
    const float* w_y     = (const float*)d_in[3];
    const float* b_y     = (const float*)d_in[4];
    const float* w_x     = (const float*)d_in[5];
    const float* b_x     = (const float*)d_in[6];
    const float* w_out   = (const float*)d_in[7];
    const float* b_out   = (const float*)d_in[8];
    const float* conv_w  = (const float*)d_in[9];
    const float* conv_b  = (const float*)d_in[10];
    const float* a_param = (const float*)d_in[11];
    const float* ig_w    = (const float*)d_in[12];
    const float* ig_b    = (const float*)d_in[13];
    const float* ag_w    = (const float*)d_in[14];
    const float* ag_b    = (const float*)d_in[15];
    float* out = (float*)d_out;

    float *p_xb, *p_yb, *p_gl;
    __half *p_xh, *p_coh, *p_nxh, *p_wxh, *p_wyh, *p_woh, *p_gwh;
    cudaGetSymbolAddress((void**)&p_xb,  g_xb);
    cudaGetSymbolAddress((void**)&p_yb,  g_yb);
    cudaGetSymbolAddress((void**)&p_gl,  g_gl);
    cudaGetSymbolAddress((void**)&p_xh,  g_xh);
    cudaGetSymbolAddress((void**)&p_coh, g_coh);
    cudaGetSymbolAddress((void**)&p_nxh, g_nxh);
    cudaGetSymbolAddress((void**)&p_wxh, g_wxh);
    cudaGetSymbolAddress((void**)&p_wyh, g_wyh);
    cudaGetSymbolAddress((void**)&p_woh, g_woh);
    cudaGetSymbolAddress((void**)&p_gwh, g_gwh);

    cudaFuncSetAttribute(gemm_f16, cudaFuncAttributeMaxDynamicSharedMemorySize, GSMEM);

    reset_kernel<<<(TOK + 255) / 256, 256>>>(pos);

    // fp32 -> fp16 conversions
    const int WN4 = DDIM * DDIM / 4;         // 1.64M
    const int XN4 = TOK * DDIM / 4;          // 5.24M
    const int GN4 = 2560 * BW / 4;           // 163840
    f2h_kernel<<<(XN4 + 255) / 256, 256>>>(x_in, p_xh, XN4);
    f2h_kernel<<<(WN4 + 255) / 256, 256>>>(w_x, p_wxh, WN4);
    f2h_kernel<<<(WN4 + 255) / 256, 256>>>(w_y, p_wyh, WN4);
    f2h_kernel<<<(WN4 + 255) / 256, 256>>>(w_out, p_woh, WN4);
    f2h_kernel<<<(GN4 + 255) / 256, 256>>>(ig_w, p_gwh, GN4);
    f2h_kernel<<<(GN4 + 255) / 256, 256>>>(ag_w, p_gwh + (size_t)2560 * BW, GN4);

    // big GEMMs: x branch, y branch (gelu)
    dim3 gg(DDIM / 128, TOK / 128);          // (20, 64)
    gemm_f16<<<gg, 256, GSMEM>>>(p_xh, p_wxh, b_x, p_xb, DDIM, DDIM, DDIM, 0, 0);
    gemm_f16<<<gg, 256, GSMEM>>>(p_xh, p_wyh, b_y, p_yb, DDIM, DDIM, DDIM, 0, 1);

    // conv
    conv_kernel<<<(2 * (SEQB / 4) * (DDIM / 4) + 255) / 256, 256>>>(conv_w, conv_b);

    // gates GEMM (both gates flattened) + pointwise
    dim3 gq(NGATE / 128, TOK / 128);         // (40, 64)
    gemm_f16<<<gq, 256, GSMEM>>>(p_coh, p_gwh, nullptr, p_gl, BW, BW, NGATE, 1, 0);
    rglru_pw<<<(TOK * (DDIM / 4) + 255) / 256, 256>>>(ig_b, ag_b, a_param);

    // scan
    scan_phase1<<<dim3(DDIM / 256, NC, 2), 256>>>();
    scan_phase2<<<(2 * DDIM + 255) / 256, 256>>>(prev_h);
    scan_phase3<<<dim3(DDIM / 256, NC, 2), 256>>>();

    // final GEMM
    gemm_f16<<<gg, 256, GSMEM>>>(p_nxh, p_woh, b_out, out, DDIM, DDIM, DDIM, 0, 0);
}

// round 6
// speedup vs baseline: 6.0322x; 1.0951x over previous
#include <cuda_runtime.h>
#include <cuda_fp16.h>
#include <math.h>
#include <stdint.h>

#define TOK 8192
#define SEQB 4096
#define DDIM 2560
#define HEADS 10
#define BW 256
#define NC 32
#define CL 128
#define NGATE 5120   // ig (2560) ++ ag (2560)

// ---------------- scratch (static device globals; no allocation) ----------------
__device__ float  g_xb[(size_t)TOK * DDIM];    // x-branch (pre-conv) fp32
__device__ float  g_co[(size_t)TOK * DDIM];    // conv output fp32
__device__ float  g_a [(size_t)TOK * DDIM];    // recurrence decay a_t
__device__ float  g_nx[(size_t)TOK * DDIM];    // normalized x (scan input)
__device__ __half g_ybh[(size_t)TOK * DDIM];   // gelu(y-branch) fp16
__device__ __half g_glh[(size_t)TOK * NGATE];  // gate logits fp16 (ig | ag)
__device__ __half g_xh [(size_t)TOK * DDIM];   // X in half
__device__ __half g_coh[(size_t)TOK * DDIM];   // conv out in half
__device__ __half g_nxh[(size_t)TOK * DDIM];   // h*y in half (final GEMM input)
__device__ __half g_wch[(size_t)NGATE * DDIM]; // [w_x rows ; w_y rows] K-major
__device__ __half g_woh[(size_t)DDIM * DDIM];
__device__ __half g_gwh[(size_t)NGATE * BW];   // [ig rows ; ag rows] x 256 K-major
__device__ float  g_Aag[2 * NC * DDIM];
__device__ float  g_Hag[2 * NC * DDIM];
__device__ float  g_Hin[2 * NC * DDIM];
__device__ unsigned char g_reset[TOK];

// ---------------- math helpers ----------------
__device__ __forceinline__ float gelu_tanh(float x) {
    float x3 = x * x * x;
    float t = tanhf(0.7978845608028654f * (x + 0.044715f * x3));
    return 0.5f * x * (1.0f + t);
}
__device__ __forceinline__ float sigmoidf(float x) {
    return 1.0f / (1.0f + expf(-x));
}
__device__ __forceinline__ float softplusf(float x) {
    return (x > 20.0f) ? x : log1pf(expf(x));
}

// ---------------- async-copy / mma helpers (sm_80+ features only) ----------------
__device__ __forceinline__ uint32_t smem_u32(const void* p) {
    uint32_t a;
    asm("{ .reg .u64 t; cvta.to.shared.u64 t, %1; cvt.u32.u64 %0, t; }" : "=r"(a) : "l"(p));
    return a;
}
__device__ __forceinline__ void cp16(uint32_t dst, const void* src) {
    asm volatile("cp.async.ca.shared.global [%0], [%1], 16;" :: "r"(dst), "l"(src));
}
__device__ __forceinline__ void cp_commit() {
    asm volatile("cp.async.commit_group;" ::: "memory");
}
template <int N> __device__ __forceinline__ void cp_wait() {
    asm volatile("cp.async.wait_group %0;" :: "n"(N) : "memory");
}
__device__ __forceinline__ void mma_f16(float* c, const uint32_t* a, const uint32_t* b) {
    asm volatile(
        "mma.sync.aligned.m16n8k16.row.col.f32.f16.f16.f32 "
        "{%0,%1,%2,%3}, {%4,%5,%6,%7}, {%8,%9}, {%0,%1,%2,%3};"
        : "+f"(c[0]), "+f"(c[1]), "+f"(c[2]), "+f"(c[3])
        : "r"(a[0]), "r"(a[1]), "r"(a[2]), "r"(a[3]), "r"(b[0]), "r"(b[1]));
}
__device__ __forceinline__ void ldm_x4(uint32_t* r, uint32_t addr) {
    asm volatile("ldmatrix.sync.aligned.m8n8.x4.shared.b16 {%0,%1,%2,%3}, [%4];"
        : "=r"(r[0]), "=r"(r[1]), "=r"(r[2]), "=r"(r[3]) : "r"(addr));
}

// ---------------- reset-mask kernel (handles int32 or int64 position_ids) ----------------
__global__ void reset_kernel(const int* __restrict__ pos32) {
    int m = blockIdx.x * 256 + threadIdx.x;
    if (m >= TOK) return;
    bool is64 = (pos32[1] == 0 && pos32[2] == 1);
    bool r;
    if (is64) r = (pos32[2 * m] == 0 && pos32[2 * m + 1] == 0);
    else      r = (pos32[m] == 0);
    g_reset[m] = r ? 1 : 0;
}

// ---------------- fp32 -> fp16 conversion ----------------
__global__ void f2h_kernel(const float* __restrict__ src, __half* __restrict__ dst, int n4) {
    int i = blockIdx.x * 256 + threadIdx.x;
    if (i >= n4) return;
    float4 v = ((const float4*)src)[i];
    ((__half2*)dst)[2 * i]     = __floats2half2_rn(v.x, v.y);
    ((__half2*)dst)[2 * i + 1] = __floats2half2_rn(v.z, v.w);
}

// =======================================================================
// fp16 mma.sync GEMM, CTA tile 128(M) x 256(N), warp tile 64x64 (2x4),
// K-chunk 64 halves, 3-stage cp.async, ldmatrix fragment loads.
// modes: 0 = fp32 out + bias (final)
//        1 = xy-combined: col<2560 -> g_xb fp32 (+b_x); else gelu -> g_ybh
//        2 = gates: half out to g_glh, A column window = head(n)*256
// =======================================================================
#define STG_B 49152                 // 16KB A + 32KB B per stage
#define GSMEM (3 * STG_B)           // 144 KB

__global__ __launch_bounds__(256, 1) void gemm_f16(
    const __half* __restrict__ A,
    const __half* __restrict__ W,
    const float* __restrict__ bias,
    const float* __restrict__ bias2,
    float* __restrict__ outf,
    int K, int ldW, int ldc, int mode)
{
    extern __shared__ __align__(16) char smem[];
    const uint32_t sbase = smem_u32(smem);

    const int tid = threadIdx.x;
    const int lane = tid & 31;
    const int wid = tid >> 5;
    const int wm = wid & 1;          // 0..1 -> 64-row slice
    const int wn = wid >> 1;         // 0..3 -> 64-col slice
    const int m0 = blockIdx.y * 128;
    const int n0 = blockIdx.x * 256;
    const int aoff = (mode == 2) ? (((n0 % 2560) >> 8) << 8) : 0;
    const int NKC = K >> 6;

    const int lrow32 = tid >> 3;     // 0..31 (cp.async row base)
    const int chk    = tid & 7;      // 16B chunk within 128B row

    float acc[4][8][4];
#pragma unroll
    for (int i = 0; i < 4; i++)
#pragma unroll
        for (int j = 0; j < 8; j++)
#pragma unroll
            for (int q = 0; q < 4; q++) acc[i][j][q] = 0.0f;

#define LD_STAGE(s, kc)                                                           \
    {                                                                             \
        int ka = aoff + (kc) * 64 + chk * 8;                                      \
        int kb = (kc) * 64 + chk * 8;                                             \
        uint32_t sA = sbase + (s) * STG_B;                                        \
        uint32_t sB = sA + 16384;                                                 \
        _Pragma("unroll")                                                         \
        for (int i = 0; i < 4; i++) {                                             \
            int row = lrow32 + i * 32;                                            \
            cp16(sA + row * 128 + (((chk ^ row) & 7) << 4),                       \
                 A + (size_t)(m0 + row) * DDIM + ka);                             \
        }                                                                         \
        _Pragma("unroll")                                                         \
        for (int i = 0; i < 8; i++) {                                             \
            int row = lrow32 + i * 32;                                            \
            cp16(sB + row * 128 + (((chk ^ row) & 7) << 4),                       \
                 W + (size_t)(n0 + row) * ldW + kb);                              \
        }                                                                         \
        cp_commit();                                                              \
    }

    LD_STAGE(0, 0);
    LD_STAGE(1, 1);

    // ldmatrix per-lane row / k-segment mapping
    const int l15 = lane & 15;
    const int kbs = (lane >> 4) & 1;         // adds 8 to k
    int rowA128[4], rowA7[4], rowB128[4], rowB7[4];
#pragma unroll
    for (int i = 0; i < 4; i++) {
        int ra = wm * 64 + i * 16 + l15;
        rowA128[i] = ra * 128; rowA7[i] = ra & 7;
        int rb = wn * 64 + i * 16 + l15;
        rowB128[i] = rb * 128 + 16384; rowB7[i] = rb & 7;
    }

    const int g = lane >> 2;
    const int t2 = (lane & 3) * 2;

    for (int kc = 0; kc < NKC; kc++) {
        cp_wait<1>();
        __syncthreads();
        int nxt = kc + 2;
        if (nxt < NKC) {
            LD_STAGE(nxt % 3, nxt);
        } else {
            cp_commit();
        }
        const uint32_t St = sbase + (kc % 3) * STG_B;
#pragma unroll
        for (int ks = 0; ks < 4; ks++) {
            const int ksg = ks * 2 + kbs;    // k-segment index 0..7
            uint32_t af[4][4];
#pragma unroll
            for (int i = 0; i < 4; i++)
                ldm_x4(af[i], St + rowA128[i] + (((ksg ^ rowA7[i]) & 7) << 4));
            uint32_t bf[8][2];
#pragma unroll
            for (int jp = 0; jp < 4; jp++) {
                uint32_t t[4];
                ldm_x4(t, St + rowB128[jp] + (((ksg ^ rowB7[jp]) & 7) << 4));
                bf[2 * jp][0] = t[0]; bf[2 * jp + 1][0] = t[1];
                bf[2 * jp][1] = t[2]; bf[2 * jp + 1][1] = t[3];
            }
#pragma unroll
            for (int i = 0; i < 4; i++)
#pragma unroll
                for (int j = 0; j < 8; j++)
                    mma_f16(acc[i][j], af[i], bf[j]);
        }
        __syncthreads();
    }

    // epilogue
#pragma unroll
    for (int i = 0; i < 4; i++) {
        int r = m0 + wm * 64 + i * 16 + g;
#pragma unroll
        for (int j = 0; j < 8; j++) {
            int col = n0 + wn * 64 + j * 8 + t2;
            float v00 = acc[i][j][0], v01 = acc[i][j][1];
            float v10 = acc[i][j][2], v11 = acc[i][j][3];
            if (mode == 0) {
                float b0 = bias[col], b1 = bias[col + 1];
                *(float2*)(outf + (size_t)r * ldc + col)       = make_float2(v00 + b0, v01 + b1);
                *(float2*)(outf + (size_t)(r + 8) * ldc + col) = make_float2(v10 + b0, v11 + b1);
            } else if (mode == 1) {
                if (col < DDIM) {
                    float b0 = bias[col], b1 = bias[col + 1];
                    *(float2*)(g_xb + (size_t)r * DDIM + col)       = make_float2(v00 + b0, v01 + b1);
                    *(float2*)(g_xb + (size_t)(r + 8) * DDIM + col) = make_float2(v10 + b0, v11 + b1);
                } else {
                    int c2 = col - DDIM;
                    float b0 = bias2[c2], b1 = bias2[c2 + 1];
                    *(__half2*)(g_ybh + (size_t)r * DDIM + c2) =
                        __floats2half2_rn(gelu_tanh(v00 + b0), gelu_tanh(v01 + b1));
                    *(__half2*)(g_ybh + (size_t)(r + 8) * DDIM + c2) =
                        __floats2half2_rn(gelu_tanh(v10 + b0), gelu_tanh(v11 + b1));
                }
            } else {
                *(__half2*)(g_glh + (size_t)r * NGATE + col)       = __floats2half2_rn(v00, v01);
                *(__half2*)(g_glh + (size_t)(r + 8) * NGATE + col) = __floats2half2_rn(v10, v11);
            }
        }
    }
}

// ---------------- depthwise causal conv: 4 timesteps per thread ----------------
__global__ __launch_bounds__(256) void conv_kernel(const float* __restrict__ cw,
                                                   const float* __restrict__ cb) {
    const int D4 = DDIM / 4;             // 640
    const int TB = SEQB / 4;             // 1024
    int idx = blockIdx.x * 256 + threadIdx.x;
    if (idx >= 2 * TB * D4) return;
    int d4 = idx % D4;
    int tb = (idx / D4) % TB;
    int b  = idx / (D4 * TB);
    int t0 = tb * 4;
    int d0 = d4 * 4;

    float cwv[4][4];
#pragma unroll
    for (int e = 0; e < 4; e++)
#pragma unroll
        for (int k = 0; k < 4; k++) cwv[e][k] = cw[(d0 + e) * 4 + k];
    float4 cb4 = *(const float4*)(cb + d0);

    const float4* X = (const float4*)g_xb;
    float4 xv[7];
#pragma unroll
    for (int i = 0; i < 7; i++) {
        int t = t0 + i - 3;
        if (t >= 0) xv[i] = X[((size_t)(b * SEQB + t)) * D4 + d4];
        else        xv[i] = make_float4(0.f, 0.f, 0.f, 0.f);
    }

#pragma unroll
    for (int jj = 0; jj < 4; jj++) {
        float4 acc = cb4;
#pragma unroll
        for (int k = 0; k < 4; k++) {
            acc.x = fmaf(xv[jj + k].x, cwv[0][k], acc.x);
            acc.y = fmaf(xv[jj + k].y, cwv[1][k], acc.y);
            acc.z = fmaf(xv[jj + k].z, cwv[2][k], acc.z);
            acc.w = fmaf(xv[jj + k].w, cwv[3][k], acc.w);
        }
        size_t o = ((size_t)(b * SEQB + t0 + jj)) * D4 + d4;
        ((float4*)g_co)[o] = acc;
        ((__half2*)g_coh)[2 * o]     = __floats2half2_rn(acc.x, acc.y);
        ((__half2*)g_coh)[2 * o + 1] = __floats2half2_rn(acc.z, acc.w);
    }
}

// ---------------- RG-LRU pointwise (from fp16 gate logits) ----------------
__global__ __launch_bounds__(256) void rglru_pw(const float* __restrict__ ig_b,
                                                const float* __restrict__ ag_b,
                                                const float* __restrict__ a_param) {
    const int D4 = DDIM / 4;
    int idx = blockIdx.x * 256 + threadIdx.x;
    if (idx >= TOK * D4) return;
    int d4 = idx % D4, m = idx / D4;
    int d0 = d4 * 4;
    int j0 = d0 & 255;
    bool rs = (g_reset[m] != 0);

    const __half2* lp = (const __half2*)(g_glh + (size_t)m * NGATE + d0);
    const __half2* la = (const __half2*)(g_glh + (size_t)m * NGATE + 2560 + d0);
    __half2 li0 = lp[0], li1 = lp[1];
    __half2 la0 = la[0], la1 = la[1];
    float4 co = ((const float4*)g_co)[idx];
    float4 bi = *(const float4*)(ig_b + j0);
    float4 ba = *(const float4*)(ag_b + j0);
    float4 ap = *(const float4*)(a_param + d0);

    float liv[4] = {__low2float(li0), __high2float(li0), __low2float(li1), __high2float(li1)};
    float lav[4] = {__low2float(la0), __high2float(la0), __low2float(la1), __high2float(la1)};
    float cov[4] = {co.x, co.y, co.z, co.w};
    float biv[4] = {bi.x, bi.y, bi.z, bi.w};
    float bav[4] = {ba.x, ba.y, ba.z, ba.w};
    float apv[4] = {ap.x, ap.y, ap.z, ap.w};
    float nxv[4], av[4];
#pragma unroll
    for (int e = 0; e < 4; e++) {
        float gx = sigmoidf(liv[e] + biv[e]);
        float ga = sigmoidf(lav[e] + bav[e]);
        float log_a = -8.0f * ga * softplusf(apv[e]);
        float a = expf(log_a);
        float mult = rs ? 1.0f : sqrtf(fmaxf(1.0f - expf(2.0f * log_a), 0.0f));
        nxv[e] = cov[e] * gx * mult;
        av[e]  = rs ? 0.0f : a;
    }
    ((float4*)g_nx)[idx] = make_float4(nxv[0], nxv[1], nxv[2], nxv[3]);
    ((float4*)g_a)[idx]  = make_float4(av[0], av[1], av[2], av[3]);
}

// ---------------- chunked linear scan ----------------
__global__ __launch_bounds__(256) void scan_phase1() {
    int d = blockIdx.x * 256 + threadIdx.x;
    int c = blockIdx.y;
    int b = blockIdx.z;
    int base = (b * SEQB + c * CL) * DDIM + d;
    float A = 1.0f, H = 0.0f;
#pragma unroll 4
    for (int i = 0; i < CL; i++) {
        float a = g_a[base + i * DDIM];
        float x = g_nx[base + i * DDIM];
        H = fmaf(a, H, x);
        A *= a;
    }
    int o = (b * NC + c) * DDIM + d;
    g_Aag[o] = A;
    g_Hag[o] = H;
}

__global__ __launch_bounds__(256) void scan_phase2(const float* __restrict__ prev_h) {
    int t = blockIdx.x * 256 + threadIdx.x;
    if (t >= 2 * DDIM) return;
    int b = t / DDIM, d = t % DDIM;
    float h = prev_h[t];
#pragma unroll
    for (int c = 0; c < NC; c++) {
        int o = (b * NC + c) * DDIM + d;
        g_Hin[o] = h;
        h = fmaf(g_Aag[o], h, g_Hag[o]);
    }
}

__global__ __launch_bounds__(256) void scan_phase3() {
    int d = blockIdx.x * 256 + threadIdx.x;
    int c = blockIdx.y;
    int b = blockIdx.z;
    int base = (b * SEQB + c * CL) * DDIM + d;
    float h = g_Hin[(b * NC + c) * DDIM + d];
#pragma unroll 4
    for (int i = 0; i < CL; i++) {
        int o = base + i * DDIM;
        float a = g_a[o];
        float x = g_nx[o];
        h = fmaf(a, h, x);
        g_nxh[o] = __float2half(h * __half2float(g_ybh[o]));
    }
}

// ---------------- launcher ----------------
extern "C" void kernel_launch(void* const* d_in, const int* in_sizes, int n_in,
                              void* d_out, int out_size) {
    const float* x_in    = (const float*)d_in[0];
    const int*   pos     = (const int*)d_in[1];
    const float* prev_h  = (const float*)d_in[2];
    const float* w_y     = (const float*)d_in[3];
    const float* b_y     = (const float*)d_in[4];
    const float* w_x     = (const float*)d_in[5];
    const float* b_x     = (const float*)d_in[6];
    const float* w_out   = (const float*)d_in[7];
    const float* b_out   = (const float*)d_in[8];
    const float* conv_w  = (const float*)d_in[9];
    const float* conv_b  = (const float*)d_in[10];
    const float* a_param = (const float*)d_in[11];
    const float* ig_w    = (const float*)d_in[12];
    const float* ig_b    = (const float*)d_in[13];
    const float* ag_w    = (const float*)d_in[14];
    const float* ag_b    = (const float*)d_in[15];
    float* out = (float*)d_out;

    __half *p_xh, *p_coh, *p_nxh, *p_wch, *p_woh, *p_gwh;
    cudaGetSymbolAddress((void**)&p_xh,  g_xh);
    cudaGetSymbolAddress((void**)&p_coh, g_coh);
    cudaGetSymbolAddress((void**)&p_nxh, g_nxh);
    cudaGetSymbolAddress((void**)&p_wch, g_wch);
    cudaGetSymbolAddress((void**)&p_woh, g_woh);
    cudaGetSymbolAddress((void**)&p_gwh, g_gwh);

    cudaFuncSetAttribute(gemm_f16, cudaFuncAttributeMaxDynamicSharedMemorySize, GSMEM);

    reset_kernel<<<(TOK + 255) / 256, 256>>>(pos);

    // fp32 -> fp16 conversions
    const int WN4 = DDIM * DDIM / 4;
    const int XN4 = TOK * DDIM / 4;
    const int GN4 = 2560 * BW / 4;
    f2h_kernel<<<(XN4 + 255) / 256, 256>>>(x_in, p_xh, XN4);
    f2h_kernel<<<(WN4 + 255) / 256, 256>>>(w_x, p_wch, WN4);
    f2h_kernel<<<(WN4 + 255) / 256, 256>>>(w_y, p_wch + (size_t)DDIM * DDIM, WN4);
    f2h_kernel<<<(WN4 + 255) / 256, 256>>>(w_out, p_woh, WN4);
    f2h_kernel<<<(GN4 + 255) / 256, 256>>>(ig_w, p_gwh, GN4);
    f2h_kernel<<<(GN4 + 255) / 256, 256>>>(ag_w, p_gwh + (size_t)2560 * BW, GN4);

    // combined x/y GEMM (N = 5120): writes g_xb (fp32) and g_ybh (fp16, gelu)
    dim3 gxy(NGATE / 256, TOK / 128);   // (20, 64)
    gemm_f16<<<gxy, 256, GSMEM>>>(p_xh, p_wch, b_x, b_y, nullptr, DDIM, DDIM, 0, 1);

    // conv
    conv_kernel<<<(2 * (SEQB / 4) * (DDIM / 4) + 255) / 256, 256>>>(conv_w, conv_b);

    // gates GEMM (both gates, K=256) -> fp16 logits; then pointwise
    gemm_f16<<<gxy, 256, GSMEM>>>(p_coh, p_gwh, nullptr, nullptr, nullptr, BW, BW, 0, 2);
    rglru_pw<<<(TOK * (DDIM / 4) + 255) / 256, 256>>>(ig_b, ag_b, a_param);

    // scan
    scan_phase1<<<dim3(DDIM / 256, NC, 2), 256>>>();
    scan_phase2<<<(2 * DDIM + 255) / 256, 256>>>(prev_h);
    scan_phase3<<<dim3(DDIM / 256, NC, 2), 256>>>();

    // final GEMM
    dim3 gf(DDIM / 256, TOK / 128);     // (10, 64)
    gemm_f16<<<gf, 256, GSMEM>>>(p_nxh, p_woh, b_out, nullptr, out, DDIM, DDIM, DDIM, 0);
}

// round 7
// speedup vs baseline: 6.0415x; 1.0015x over previous
#include <cuda_runtime.h>
#include <cuda_fp16.h>
#include <math.h>
#include <stdint.h>

#define TOK 8192
#define SEQB 4096
#define DDIM 2560
#define HEADS 10
#define BW 256
#define NC 32
#define CL 128
#define NGATE 5120   // ig (2560) ++ ag (2560)

// ---------------- scratch (static device globals; no allocation) ----------------
__device__ float  g_a [(size_t)TOK * DDIM];    // recurrence decay a_t (fp32: error must not compound)
__device__ __half g_xbh[(size_t)TOK * DDIM];   // x-branch (pre-conv) fp16
__device__ __half g_ybh[(size_t)TOK * DDIM];   // gelu(y-branch) fp16
__device__ __half g_coh[(size_t)TOK * DDIM];   // conv out fp16
__device__ __half g_glh[(size_t)TOK * NGATE];  // gate logits fp16 (ig | ag)
__device__ __half g_nxs[(size_t)TOK * DDIM];   // normalized x (scan input) fp16
__device__ __half g_xh [(size_t)TOK * DDIM];   // X in half
__device__ __half g_nxh[(size_t)TOK * DDIM];   // h*y in half (final GEMM input)
__device__ __half g_wch[(size_t)NGATE * DDIM]; // [w_x rows ; w_y rows] K-major
__device__ __half g_woh[(size_t)DDIM * DDIM];
__device__ __half g_gwh[(size_t)NGATE * BW];   // [ig rows ; ag rows] x 256 K-major
__device__ float  g_Aag[2 * NC * DDIM];
__device__ float  g_Hag[2 * NC * DDIM];
__device__ float  g_Hin[2 * NC * DDIM];
__device__ unsigned char g_reset[TOK];

// ---------------- math helpers ----------------
__device__ __forceinline__ float gelu_tanh(float x) {
    float x3 = x * x * x;
    float t = tanhf(0.7978845608028654f * (x + 0.044715f * x3));
    return 0.5f * x * (1.0f + t);
}
__device__ __forceinline__ float sigmoidf(float x) {
    return 1.0f / (1.0f + expf(-x));
}
__device__ __forceinline__ float softplusf(float x) {
    return (x > 20.0f) ? x : log1pf(expf(x));
}

// ---------------- async-copy / mma helpers (sm_80+ features only) ----------------
__device__ __forceinline__ uint32_t smem_u32(const void* p) {
    uint32_t a;
    asm("{ .reg .u64 t; cvta.to.shared.u64 t, %1; cvt.u32.u64 %0, t; }" : "=r"(a) : "l"(p));
    return a;
}
__device__ __forceinline__ void cp16(uint32_t dst, const void* src) {
    asm volatile("cp.async.ca.shared.global [%0], [%1], 16;" :: "r"(dst), "l"(src));
}
__device__ __forceinline__ void cp_commit() {
    asm volatile("cp.async.commit_group;" ::: "memory");
}
template <int N> __device__ __forceinline__ void cp_wait() {
    asm volatile("cp.async.wait_group %0;" :: "n"(N) : "memory");
}
__device__ __forceinline__ void mma_f16(float* c, const uint32_t* a, const uint32_t* b) {
    asm volatile(
        "mma.sync.aligned.m16n8k16.row.col.f32.f16.f16.f32 "
        "{%0,%1,%2,%3}, {%4,%5,%6,%7}, {%8,%9}, {%0,%1,%2,%3};"
        : "+f"(c[0]), "+f"(c[1]), "+f"(c[2]), "+f"(c[3])
        : "r"(a[0]), "r"(a[1]), "r"(a[2]), "r"(a[3]), "r"(b[0]), "r"(b[1]));
}
__device__ __forceinline__ void ldm_x4(uint32_t* r, uint32_t addr) {
    asm volatile("ldmatrix.sync.aligned.m8n8.x4.shared.b16 {%0,%1,%2,%3}, [%4];"
        : "=r"(r[0]), "=r"(r[1]), "=r"(r[2]), "=r"(r[3]) : "r"(addr));
}

// ---------------- reset-mask kernel (handles int32 or int64 position_ids) ----------------
__global__ void reset_kernel(const int* __restrict__ pos32) {
    int m = blockIdx.x * 256 + threadIdx.x;
    if (m >= TOK) return;
    bool is64 = (pos32[1] == 0 && pos32[2] == 1);
    bool r;
    if (is64) r = (pos32[2 * m] == 0 && pos32[2 * m + 1] == 0);
    else      r = (pos32[m] == 0);
    g_reset[m] = r ? 1 : 0;
}

// ---------------- fp32 -> fp16 conversion ----------------
__global__ void f2h_kernel(const float* __restrict__ src, __half* __restrict__ dst, int n4) {
    int i = blockIdx.x * 256 + threadIdx.x;
    if (i >= n4) return;
    float4 v = ((const float4*)src)[i];
    ((__half2*)dst)[2 * i]     = __floats2half2_rn(v.x, v.y);
    ((__half2*)dst)[2 * i + 1] = __floats2half2_rn(v.z, v.w);
}

// =======================================================================
// fp16 mma.sync GEMM, CTA tile 128(M) x 256(N), warp tile 64x64 (2x4),
// K-chunk 64 halves, 3-stage cp.async, ldmatrix fragment loads.
// modes: 0 = fp32 out + bias (final)
//        1 = xy-combined: col<2560 -> g_xbh fp16 (+b_x); else gelu -> g_ybh
//        2 = gates: half out to g_glh, A column window = head(n)*256
// =======================================================================
#define STG_B 49152                 // 16KB A + 32KB B per stage
#define GSMEM (3 * STG_B)           // 144 KB

__global__ __launch_bounds__(256, 1) void gemm_f16(
    const __half* __restrict__ A,
    const __half* __restrict__ W,
    const float* __restrict__ bias,
    const float* __restrict__ bias2,
    float* __restrict__ outf,
    int K, int ldW, int ldc, int mode)
{
    extern __shared__ __align__(16) char smem[];
    const uint32_t sbase = smem_u32(smem);

    const int tid = threadIdx.x;
    const int lane = tid & 31;
    const int wid = tid >> 5;
    const int wm = wid & 1;          // 0..1 -> 64-row slice
    const int wn = wid >> 1;         // 0..3 -> 64-col slice
    const int m0 = blockIdx.y * 128;
    const int n0 = blockIdx.x * 256;
    const int aoff = (mode == 2) ? (((n0 % 2560) >> 8) << 8) : 0;
    const int NKC = K >> 6;

    const int lrow32 = tid >> 3;     // 0..31 (cp.async row base)
    const int chk    = tid & 7;      // 16B chunk within 128B row

    float acc[4][8][4];
#pragma unroll
    for (int i = 0; i < 4; i++)
#pragma unroll
        for (int j = 0; j < 8; j++)
#pragma unroll
            for (int q = 0; q < 4; q++) acc[i][j][q] = 0.0f;

#define LD_STAGE(s, kc)                                                           \
    {                                                                             \
        int ka = aoff + (kc) * 64 + chk * 8;                                      \
        int kb = (kc) * 64 + chk * 8;                                             \
        uint32_t sA = sbase + (s) * STG_B;                                        \
        uint32_t sB = sA + 16384;                                                 \
        _Pragma("unroll")                                                         \
        for (int i = 0; i < 4; i++) {                                             \
            int row = lrow32 + i * 32;                                            \
            cp16(sA + row * 128 + (((chk ^ row) & 7) << 4),                       \
                 A + (size_t)(m0 + row) * DDIM + ka);                             \
        }                                                                         \
        _Pragma("unroll")                                                         \
        for (int i = 0; i < 8; i++) {                                             \
            int row = lrow32 + i * 32;                                            \
            cp16(sB + row * 128 + (((chk ^ row) & 7) << 4),                       \
                 W + (size_t)(n0 + row) * ldW + kb);                              \
        }                                                                         \
        cp_commit();                                                              \
    }

    LD_STAGE(0, 0);
    LD_STAGE(1, 1);

    const int l15 = lane & 15;
    const int kbs = (lane >> 4) & 1;
    int rowA128[4], rowA7[4], rowB128[4], rowB7[4];
#pragma unroll
    for (int i = 0; i < 4; i++) {
        int ra = wm * 64 + i * 16 + l15;
        rowA128[i] = ra * 128; rowA7[i] = ra & 7;
        int rb = wn * 64 + i * 16 + l15;
        rowB128[i] = rb * 128 + 16384; rowB7[i] = rb & 7;
    }

    const int g = lane >> 2;
    const int t2 = (lane & 3) * 2;

    for (int kc = 0; kc < NKC; kc++) {
        cp_wait<1>();
        __syncthreads();
        int nxt = kc + 2;
        if (nxt < NKC) {
            LD_STAGE(nxt % 3, nxt);
        } else {
            cp_commit();
        }
        const uint32_t St = sbase + (kc % 3) * STG_B;
#pragma unroll
        for (int ks = 0; ks < 4; ks++) {
            const int ksg = ks * 2 + kbs;
            uint32_t af[4][4];
#pragma unroll
            for (int i = 0; i < 4; i++)
                ldm_x4(af[i], St + rowA128[i] + (((ksg ^ rowA7[i]) & 7) << 4));
            uint32_t bf[8][2];
#pragma unroll
            for (int jp = 0; jp < 4; jp++) {
                uint32_t t[4];
                ldm_x4(t, St + rowB128[jp] + (((ksg ^ rowB7[jp]) & 7) << 4));
                bf[2 * jp][0] = t[0]; bf[2 * jp + 1][0] = t[1];
                bf[2 * jp][1] = t[2]; bf[2 * jp + 1][1] = t[3];
            }
#pragma unroll
            for (int i = 0; i < 4; i++)
#pragma unroll
                for (int j = 0; j < 8; j++)
                    mma_f16(acc[i][j], af[i], bf[j]);
        }
        __syncthreads();
    }

    // epilogue
#pragma unroll
    for (int i = 0; i < 4; i++) {
        int r = m0 + wm * 64 + i * 16 + g;
#pragma unroll
        for (int j = 0; j < 8; j++) {
            int col = n0 + wn * 64 + j * 8 + t2;
            float v00 = acc[i][j][0], v01 = acc[i][j][1];
            float v10 = acc[i][j][2], v11 = acc[i][j][3];
            if (mode == 0) {
                float b0 = bias[col], b1 = bias[col + 1];
                *(float2*)(outf + (size_t)r * ldc + col)       = make_float2(v00 + b0, v01 + b1);
                *(float2*)(outf + (size_t)(r + 8) * ldc + col) = make_float2(v10 + b0, v11 + b1);
            } else if (mode == 1) {
                if (col < DDIM) {
                    float b0 = bias[col], b1 = bias[col + 1];
                    *(__half2*)(g_xbh + (size_t)r * DDIM + col) =
                        __floats2half2_rn(v00 + b0, v01 + b1);
                    *(__half2*)(g_xbh + (size_t)(r + 8) * DDIM + col) =
                        __floats2half2_rn(v10 + b0, v11 + b1);
                } else {
                    int c2 = col - DDIM;
                    float b0 = bias2[c2], b1 = bias2[c2 + 1];
                    *(__half2*)(g_ybh + (size_t)r * DDIM + c2) =
                        __floats2half2_rn(gelu_tanh(v00 + b0), gelu_tanh(v01 + b1));
                    *(__half2*)(g_ybh + (size_t)(r + 8) * DDIM + c2) =
                        __floats2half2_rn(gelu_tanh(v10 + b0), gelu_tanh(v11 + b1));
                }
            } else {
                *(__half2*)(g_glh + (size_t)r * NGATE + col)       = __floats2half2_rn(v00, v01);
                *(__half2*)(g_glh + (size_t)(r + 8) * NGATE + col) = __floats2half2_rn(v10, v11);
            }
        }
    }
}

// ---------------- depthwise causal conv (fp16 in/out), 4 timesteps/thread ----------------
__global__ __launch_bounds__(256) void conv_kernel(const float* __restrict__ cw,
                                                   const float* __restrict__ cb) {
    const int D4 = DDIM / 4;             // 640 groups of 4 halves
    const int TB = SEQB / 4;             // 1024
    int idx = blockIdx.x * 256 + threadIdx.x;
    if (idx >= 2 * TB * D4) return;
    int d4 = idx % D4;
    int tb = (idx / D4) % TB;
    int b  = idx / (D4 * TB);
    int t0 = tb * 4;
    int d0 = d4 * 4;

    float cwv[4][4];
#pragma unroll
    for (int e = 0; e < 4; e++)
#pragma unroll
        for (int k = 0; k < 4; k++) cwv[e][k] = cw[(d0 + e) * 4 + k];
    float4 cb4 = *(const float4*)(cb + d0);

    const __half2* X2 = (const __half2*)g_xbh;
    float4 xv[7];
#pragma unroll
    for (int i = 0; i < 7; i++) {
        int t = t0 + i - 3;
        if (t >= 0) {
            size_t o = ((size_t)(b * SEQB + t)) * (DDIM / 2) + d4 * 2;
            __half2 h0 = X2[o], h1 = X2[o + 1];
            xv[i] = make_float4(__low2float(h0), __high2float(h0),
                                __low2float(h1), __high2float(h1));
        } else {
            xv[i] = make_float4(0.f, 0.f, 0.f, 0.f);
        }
    }

#pragma unroll
    for (int jj = 0; jj < 4; jj++) {
        float4 acc = cb4;
#pragma unroll
        for (int k = 0; k < 4; k++) {
            acc.x = fmaf(xv[jj + k].x, cwv[0][k], acc.x);
            acc.y = fmaf(xv[jj + k].y, cwv[1][k], acc.y);
            acc.z = fmaf(xv[jj + k].z, cwv[2][k], acc.z);
            acc.w = fmaf(xv[jj + k].w, cwv[3][k], acc.w);
        }
        size_t o = ((size_t)(b * SEQB + t0 + jj)) * (DDIM / 2) + d4 * 2;
        ((__half2*)g_coh)[o]     = __floats2half2_rn(acc.x, acc.y);
        ((__half2*)g_coh)[o + 1] = __floats2half2_rn(acc.z, acc.w);
    }
}

// ---------------- fused RG-LRU pointwise + scan phase 1 ----------------
// one thread per (d, chunk, batch): walks CL=128 timesteps, computes a/nx
// from fp16 logits + fp16 conv-out, accumulates chunk aggregates.
__global__ __launch_bounds__(256) void rglru_scan1(const float* __restrict__ ig_b,
                                                   const float* __restrict__ ag_b,
                                                   const float* __restrict__ a_param) {
    int d = blockIdx.x * 256 + threadIdx.x;   // 0..2559
    int c = blockIdx.y;
    int b = blockIdx.z;
    const float bi = ig_b[d & 255];
    const float ba = ag_b[d & 255];
    const float sp = softplusf(a_param[d]);
    const int mbase = b * SEQB + c * CL;

    float A = 1.0f, H = 0.0f;
#pragma unroll 4
    for (int i = 0; i < CL; i++) {
        int m = mbase + i;
        size_t gl = (size_t)m * NGATE + d;
        float li = __half2float(g_glh[gl]);
        float la = __half2float(g_glh[gl + 2560]);
        float co = __half2float(g_coh[(size_t)m * DDIM + d]);
        bool rs = (g_reset[m] != 0);
        float gx = sigmoidf(li + bi);
        float ga = sigmoidf(la + ba);
        float log_a = -8.0f * ga * sp;
        float a = rs ? 0.0f : expf(log_a);
        float mult = rs ? 1.0f : sqrtf(fmaxf(1.0f - expf(2.0f * log_a), 0.0f));
        float nx = co * gx * mult;
        size_t o = (size_t)m * DDIM + d;
        g_a[o] = a;
        g_nxs[o] = __float2half(nx);
        H = fmaf(a, H, nx);
        A *= a;
    }
    int o = (b * NC + c) * DDIM + d;
    g_Aag[o] = A;
    g_Hag[o] = H;
}

// ---------------- cross-chunk scan ----------------
__global__ __launch_bounds__(256) void scan_phase2(const float* __restrict__ prev_h) {
    int t = blockIdx.x * 256 + threadIdx.x;
    if (t >= 2 * DDIM) return;
    int b = t / DDIM, d = t % DDIM;
    float h = prev_h[t];
#pragma unroll
    for (int c = 0; c < NC; c++) {
        int o = (b * NC + c) * DDIM + d;
        g_Hin[o] = h;
        h = fmaf(g_Aag[o], h, g_Hag[o]);
    }
}

__global__ __launch_bounds__(256) void scan_phase3() {
    int d = blockIdx.x * 256 + threadIdx.x;
    int c = blockIdx.y;
    int b = blockIdx.z;
    int base = (b * SEQB + c * CL) * DDIM + d;
    float h = g_Hin[(b * NC + c) * DDIM + d];
#pragma unroll 4
    for (int i = 0; i < CL; i++) {
        int o = base + i * DDIM;
        float a = g_a[o];
        float x = __half2float(g_nxs[o]);
        h = fmaf(a, h, x);
        g_nxh[o] = __float2half(h * __half2float(g_ybh[o]));
    }
}

// ---------------- launcher ----------------
extern "C" void kernel_launch(void* const* d_in, const int* in_sizes, int n_in,
                              void* d_out, int out_size) {
    const float* x_in    = (const float*)d_in[0];
    const int*   pos     = (const int*)d_in[1];
    const float* prev_h  = (const float*)d_in[2];
    const float* w_y     = (const float*)d_in[3];
    const float* b_y     = (const float*)d_in[4];
    const float* w_x     = (const float*)d_in[5];
    const float* b_x     = (const float*)d_in[6];
    const float* w_out   = (const float*)d_in[7];
    const float* b_out   = (const float*)d_in[8];
    const float* conv_w  = (const float*)d_in[9];
    const float* conv_b  = (const float*)d_in[10];
    const float* a_param = (const float*)d_in[11];
    const float* ig_w    = (const float*)d_in[12];
    const float* ig_b    = (const float*)d_in[13];
    const float* ag_w    = (const float*)d_in[14];
    const float* ag_b    = (const float*)d_in[15];
    float* out = (float*)d_out;

    __half *p_xh, *p_coh, *p_nxh, *p_wch, *p_woh, *p_gwh;
    cudaGetSymbolAddress((void**)&p_xh,  g_xh);
    cudaGetSymbolAddress((void**)&p_coh, g_coh);
    cudaGetSymbolAddress((void**)&p_nxh, g_nxh);
    cudaGetSymbolAddress((void**)&p_wch, g_wch);
    cudaGetSymbolAddress((void**)&p_woh, g_woh);
    cudaGetSymbolAddress((void**)&p_gwh, g_gwh);

    cudaFuncSetAttribute(gemm_f16, cudaFuncAttributeMaxDynamicSharedMemorySize, GSMEM);

    reset_kernel<<<(TOK + 255) / 256, 256>>>(pos);

    // fp32 -> fp16 conversions
    const int WN4 = DDIM * DDIM / 4;
    const int XN4 = TOK * DDIM / 4;
    const int GN4 = 2560 * BW / 4;
    f2h_kernel<<<(XN4 + 255) / 256, 256>>>(x_in, p_xh, XN4);
    f2h_kernel<<<(WN4 + 255) / 256, 256>>>(w_x, p_wch, WN4);
    f2h_kernel<<<(WN4 + 255) / 256, 256>>>(w_y, p_wch + (size_t)DDIM * DDIM, WN4);
    f2h_kernel<<<(WN4 + 255) / 256, 256>>>(w_out, p_woh, WN4);
    f2h_kernel<<<(GN4 + 255) / 256, 256>>>(ig_w, p_gwh, GN4);
    f2h_kernel<<<(GN4 + 255) / 256, 256>>>(ag_w, p_gwh + (size_t)2560 * BW, GN4);

    // combined x/y GEMM (N = 5120): writes g_xbh (fp16) and g_ybh (fp16, gelu)
    dim3 gxy(NGATE / 256, TOK / 128);   // (20, 64)
    gemm_f16<<<gxy, 256, GSMEM>>>(p_xh, p_wch, b_x, b_y, nullptr, DDIM, DDIM, 0, 1);

    // conv (fp16 in, fp16 out)
    conv_kernel<<<(2 * (SEQB / 4) * (DDIM / 4) + 255) / 256, 256>>>(conv_w, conv_b);

    // gates GEMM (both gates, K=256) -> fp16 logits
    gemm_f16<<<gxy, 256, GSMEM>>>(p_coh, p_gwh, nullptr, nullptr, nullptr, BW, BW, 0, 2);

    // fused pointwise + chunk-scan, cross-chunk scan, fix-up
    rglru_scan1<<<dim3(DDIM / 256, NC, 2), 256>>>(ig_b, ag_b, a_param);
    scan_phase2<<<(2 * DDIM + 255) / 256, 256>>>(prev_h);
    scan_phase3<<<dim3(DDIM / 256, NC, 2), 256>>>();

    // final GEMM
    dim3 gf(DDIM / 256, TOK / 128);     // (10, 64)
    gemm_f16<<<gf, 256, GSMEM>>>(p_nxh, p_woh, b_out, nullptr, out, DDIM, DDIM, DDIM, 0);
}

// round 8
// speedup vs baseline: 6.1865x; 1.0240x over previous
#include <cuda_runtime.h>
#include <cuda_fp16.h>
#include <math.h>
#include <stdint.h>

#define TOK 8192
#define SEQB 4096
#define DDIM 2560
#define HEADS 10
#define BW 256
#define NC 32
#define CL 128
#define NGATE 5120   // ig (2560) ++ ag (2560)

// ---------------- scratch (static device globals; no allocation) ----------------
__device__ float  g_a [(size_t)TOK * DDIM];    // recurrence decay a_t (fp32)
__device__ __half g_xbh[(size_t)TOK * DDIM];   // x-branch (pre-conv) fp16
__device__ __half g_ybh[(size_t)TOK * DDIM];   // gelu(y-branch) fp16
__device__ __half g_coh[(size_t)TOK * DDIM];   // conv out fp16
__device__ __half g_glh[(size_t)TOK * NGATE];  // gate logits fp16 (ig | ag)
__device__ __half g_nxs[(size_t)TOK * DDIM];   // normalized x (scan input) fp16
__device__ __half g_xh [(size_t)TOK * DDIM];   // X in half
__device__ __half g_nxh[(size_t)TOK * DDIM];   // h*y in half (final GEMM input)
__device__ __half g_wch[(size_t)NGATE * DDIM]; // [w_x rows ; w_y rows] K-major
__device__ __half g_woh[(size_t)DDIM * DDIM];
__device__ __half g_gwh[(size_t)NGATE * BW];   // [ig rows ; ag rows] x 256 K-major
__device__ float  g_Aag[2 * NC * DDIM];
__device__ float  g_Hag[2 * NC * DDIM];
__device__ float  g_Hin[2 * NC * DDIM];
__device__ unsigned char g_reset[TOK];

// ---------------- fast math helpers (1-MUFU HW approx) ----------------
__device__ __forceinline__ float tanh_fast(float x) {
    float r;
    asm("tanh.approx.f32 %0, %1;" : "=f"(r) : "f"(x));
    return r;
}
__device__ __forceinline__ float sqrt_fast(float x) {
    float r;
    asm("sqrt.approx.f32 %0, %1;" : "=f"(r) : "f"(x));
    return r;
}
__device__ __forceinline__ float gelu_tanh(float x) {
    float inner = 0.7978845608028654f * (x + 0.044715f * x * x * x);
    return 0.5f * x * (1.0f + tanh_fast(inner));
}
__device__ __forceinline__ float softplusf(float x) {
    return (x > 20.0f) ? x : log1pf(expf(x));
}

// ---------------- async-copy / mma helpers (sm_80+ features only) ----------------
__device__ __forceinline__ uint32_t smem_u32(const void* p) {
    uint32_t a;
    asm("{ .reg .u64 t; cvta.to.shared.u64 t, %1; cvt.u32.u64 %0, t; }" : "=r"(a) : "l"(p));
    return a;
}
__device__ __forceinline__ void cp16(uint32_t dst, const void* src) {
    asm volatile("cp.async.ca.shared.global [%0], [%1], 16;" :: "r"(dst), "l"(src));
}
__device__ __forceinline__ void cp_commit() {
    asm volatile("cp.async.commit_group;" ::: "memory");
}
template <int N> __device__ __forceinline__ void cp_wait() {
    asm volatile("cp.async.wait_group %0;" :: "n"(N) : "memory");
}
__device__ __forceinline__ void mma_f16(float* c, const uint32_t* a, const uint32_t* b) {
    asm volatile(
        "mma.sync.aligned.m16n8k16.row.col.f32.f16.f16.f32 "
        "{%0,%1,%2,%3}, {%4,%5,%6,%7}, {%8,%9}, {%0,%1,%2,%3};"
        : "+f"(c[0]), "+f"(c[1]), "+f"(c[2]), "+f"(c[3])
        : "r"(a[0]), "r"(a[1]), "r"(a[2]), "r"(a[3]), "r"(b[0]), "r"(b[1]));
}
__device__ __forceinline__ void ldm_x4(uint32_t* r, uint32_t addr) {
    asm volatile("ldmatrix.sync.aligned.m8n8.x4.shared.b16 {%0,%1,%2,%3}, [%4];"
        : "=r"(r[0]), "=r"(r[1]), "=r"(r[2]), "=r"(r[3]) : "r"(addr));
}

// ---------------- reset-mask kernel (handles int32 or int64 position_ids) ----------------
__global__ void reset_kernel(const int* __restrict__ pos32) {
    int m = blockIdx.x * 256 + threadIdx.x;
    if (m >= TOK) return;
    bool is64 = (pos32[1] == 0 && pos32[2] == 1);
    bool r;
    if (is64) r = (pos32[2 * m] == 0 && pos32[2 * m + 1] == 0);
    else      r = (pos32[m] == 0);
    g_reset[m] = r ? 1 : 0;
}

// ---------------- fp32 -> fp16 conversion ----------------
__global__ void f2h_kernel(const float* __restrict__ src, __half* __restrict__ dst, int n4) {
    int i = blockIdx.x * 256 + threadIdx.x;
    if (i >= n4) return;
    float4 v = ((const float4*)src)[i];
    ((__half2*)dst)[2 * i]     = __floats2half2_rn(v.x, v.y);
    ((__half2*)dst)[2 * i + 1] = __floats2half2_rn(v.z, v.w);
}

// =======================================================================
// fp16 mma.sync GEMM, CTA tile 128(M) x 256(N), warp tile 64x64 (2x4),
// K-chunk 64 halves, 3-stage cp.async, ldmatrix fragment loads.
// modes: 0 = fp32 out + bias (final)
//        1 = xy-combined: col<2560 -> g_xbh fp16 (+b_x); else gelu -> g_ybh
//        2 = gates: half out to g_glh, A column window = head(n)*256
// =======================================================================
#define STG_B 49152                 // 16KB A + 32KB B per stage
#define GSMEM (3 * STG_B)           // 144 KB

__global__ __launch_bounds__(256, 1) void gemm_f16(
    const __half* __restrict__ A,
    const __half* __restrict__ W,
    const float* __restrict__ bias,
    const float* __restrict__ bias2,
    float* __restrict__ outf,
    int K, int ldW, int ldc, int mode)
{
    extern __shared__ __align__(16) char smem[];
    const uint32_t sbase = smem_u32(smem);

    const int tid = threadIdx.x;
    const int lane = tid & 31;
    const int wid = tid >> 5;
    const int wm = wid & 1;          // 0..1 -> 64-row slice
    const int wn = wid >> 1;         // 0..3 -> 64-col slice
    const int m0 = blockIdx.y * 128;
    const int n0 = blockIdx.x * 256;
    const int aoff = (mode == 2) ? (((n0 % 2560) >> 8) << 8) : 0;
    const int NKC = K >> 6;

    const int lrow32 = tid >> 3;     // 0..31 (cp.async row base)
    const int chk    = tid & 7;      // 16B chunk within 128B row

    float acc[4][8][4];
#pragma unroll
    for (int i = 0; i < 4; i++)
#pragma unroll
        for (int j = 0; j < 8; j++)
#pragma unroll
            for (int q = 0; q < 4; q++) acc[i][j][q] = 0.0f;

#define LD_STAGE(s, kc)                                                           \
    {                                                                             \
        int ka = aoff + (kc) * 64 + chk * 8;                                      \
        int kb = (kc) * 64 + chk * 8;                                             \
        uint32_t sA = sbase + (s) * STG_B;                                        \
        uint32_t sB = sA + 16384;                                                 \
        _Pragma("unroll")                                                         \
        for (int i = 0; i < 4; i++) {                                             \
            int row = lrow32 + i * 32;                                            \
            cp16(sA + row * 128 + (((chk ^ row) & 7) << 4),                       \
                 A + (size_t)(m0 + row) * DDIM + ka);                             \
        }                                                                         \
        _Pragma("unroll")                                                         \
        for (int i = 0; i < 8; i++) {                                             \
            int row = lrow32 + i * 32;                                            \
            cp16(sB + row * 128 + (((chk ^ row) & 7) << 4),                       \
                 W + (size_t)(n0 + row) * ldW + kb);                              \
        }                                                                         \
        cp_commit();                                                              \
    }

    LD_STAGE(0, 0);
    LD_STAGE(1, 1);

    const int l15 = lane & 15;
    const int kbs = (lane >> 4) & 1;
    int rowA128[4], rowA7[4], rowB128[4], rowB7[4];
#pragma unroll
    for (int i = 0; i < 4; i++) {
        int ra = wm * 64 + i * 16 + l15;
        rowA128[i] = ra * 128; rowA7[i] = ra & 7;
        int rb = wn * 64 + i * 16 + l15;
        rowB128[i] = rb * 128 + 16384; rowB7[i] = rb & 7;
    }

    const int g = lane >> 2;
    const int t2 = (lane & 3) * 2;

    for (int kc = 0; kc < NKC; kc++) {
        cp_wait<1>();
        __syncthreads();
        int nxt = kc + 2;
        if (nxt < NKC) {
            LD_STAGE(nxt % 3, nxt);
        } else {
            cp_commit();
        }
        const uint32_t St = sbase + (kc % 3) * STG_B;
#pragma unroll
        for (int ks = 0; ks < 4; ks++) {
            const int ksg = ks * 2 + kbs;
            uint32_t af[4][4];
#pragma unroll
            for (int i = 0; i < 4; i++)
                ldm_x4(af[i], St + rowA128[i] + (((ksg ^ rowA7[i]) & 7) << 4));
            uint32_t bf[8][2];
#pragma unroll
            for (int jp = 0; jp < 4; jp++) {
                uint32_t t[4];
                ldm_x4(t, St + rowB128[jp] + (((ksg ^ rowB7[jp]) & 7) << 4));
                bf[2 * jp][0] = t[0]; bf[2 * jp + 1][0] = t[1];
                bf[2 * jp][1] = t[2]; bf[2 * jp + 1][1] = t[3];
            }
#pragma unroll
            for (int i = 0; i < 4; i++)
#pragma unroll
                for (int j = 0; j < 8; j++)
                    mma_f16(acc[i][j], af[i], bf[j]);
        }
        __syncthreads();
    }

    // epilogue
#pragma unroll
    for (int i = 0; i < 4; i++) {
        int r = m0 + wm * 64 + i * 16 + g;
#pragma unroll
        for (int j = 0; j < 8; j++) {
            int col = n0 + wn * 64 + j * 8 + t2;
            float v00 = acc[i][j][0], v01 = acc[i][j][1];
            float v10 = acc[i][j][2], v11 = acc[i][j][3];
            if (mode == 0) {
                float b0 = bias[col], b1 = bias[col + 1];
                *(float2*)(outf + (size_t)r * ldc + col)       = make_float2(v00 + b0, v01 + b1);
                *(float2*)(outf + (size_t)(r + 8) * ldc + col) = make_float2(v10 + b0, v11 + b1);
            } else if (mode == 1) {
                if (col < DDIM) {
                    float b0 = bias[col], b1 = bias[col + 1];
                    *(__half2*)(g_xbh + (size_t)r * DDIM + col) =
                        __floats2half2_rn(v00 + b0, v01 + b1);
                    *(__half2*)(g_xbh + (size_t)(r + 8) * DDIM + col) =
                        __floats2half2_rn(v10 + b0, v11 + b1);
                } else {
                    int c2 = col - DDIM;
                    float b0 = bias2[c2], b1 = bias2[c2 + 1];
                    *(__half2*)(g_ybh + (size_t)r * DDIM + c2) =
                        __floats2half2_rn(gelu_tanh(v00 + b0), gelu_tanh(v01 + b1));
                    *(__half2*)(g_ybh + (size_t)(r + 8) * DDIM + c2) =
                        __floats2half2_rn(gelu_tanh(v10 + b0), gelu_tanh(v11 + b1));
                }
            } else {
                *(__half2*)(g_glh + (size_t)r * NGATE + col)       = __floats2half2_rn(v00, v01);
                *(__half2*)(g_glh + (size_t)(r + 8) * NGATE + col) = __floats2half2_rn(v10, v11);
            }
        }
    }
}

// ---------------- depthwise causal conv (fp16 in/out), 4 timesteps/thread ----------------
__global__ __launch_bounds__(256) void conv_kernel(const float* __restrict__ cw,
                                                   const float* __restrict__ cb) {
    const int D4 = DDIM / 4;             // 640 groups of 4 halves
    const int TB = SEQB / 4;             // 1024
    int idx = blockIdx.x * 256 + threadIdx.x;
    if (idx >= 2 * TB * D4) return;
    int d4 = idx % D4;
    int tb = (idx / D4) % TB;
    int b  = idx / (D4 * TB);
    int t0 = tb * 4;
    int d0 = d4 * 4;

    float cwv[4][4];
#pragma unroll
    for (int e = 0; e < 4; e++)
#pragma unroll
        for (int k = 0; k < 4; k++) cwv[e][k] = cw[(d0 + e) * 4 + k];
    float4 cb4 = *(const float4*)(cb + d0);

    const __half2* X2 = (const __half2*)g_xbh;
    float4 xv[7];
#pragma unroll
    for (int i = 0; i < 7; i++) {
        int t = t0 + i - 3;
        if (t >= 0) {
            size_t o = ((size_t)(b * SEQB + t)) * (DDIM / 2) + d4 * 2;
            __half2 h0 = X2[o], h1 = X2[o + 1];
            xv[i] = make_float4(__low2float(h0), __high2float(h0),
                                __low2float(h1), __high2float(h1));
        } else {
            xv[i] = make_float4(0.f, 0.f, 0.f, 0.f);
        }
    }

#pragma unroll
    for (int jj = 0; jj < 4; jj++) {
        float4 acc = cb4;
#pragma unroll
        for (int k = 0; k < 4; k++) {
            acc.x = fmaf(xv[jj + k].x, cwv[0][k], acc.x);
            acc.y = fmaf(xv[jj + k].y, cwv[1][k], acc.y);
            acc.z = fmaf(xv[jj + k].z, cwv[2][k], acc.z);
            acc.w = fmaf(xv[jj + k].w, cwv[3][k], acc.w);
        }
        size_t o = ((size_t)(b * SEQB + t0 + jj)) * (DDIM / 2) + d4 * 2;
        ((__half2*)g_coh)[o]     = __floats2half2_rn(acc.x, acc.y);
        ((__half2*)g_coh)[o + 1] = __floats2half2_rn(acc.z, acc.w);
    }
}

// ---------------- fused RG-LRU pointwise + scan phase 1 (fast-math) ----------------
__global__ __launch_bounds__(256) void rglru_scan1(const float* __restrict__ ig_b,
                                                   const float* __restrict__ ag_b,
                                                   const float* __restrict__ a_param) {
    int d = blockIdx.x * 256 + threadIdx.x;   // 0..2559
    int c = blockIdx.y;
    int b = blockIdx.z;
    const float bi = ig_b[d & 255];
    const float ba = ag_b[d & 255];
    const float sp8 = -8.0f * softplusf(a_param[d]);
    const int mbase = b * SEQB + c * CL;

    float A = 1.0f, H = 0.0f;
#pragma unroll 4
    for (int i = 0; i < CL; i++) {
        int m = mbase + i;
        size_t gl = (size_t)m * NGATE + d;
        float li = __half2float(g_glh[gl]);
        float la = __half2float(g_glh[gl + 2560]);
        float co = __half2float(g_coh[(size_t)m * DDIM + d]);
        bool rs = (g_reset[m] != 0);
        // gx: 1-MUFU sigmoid via tanh.approx (benign path)
        float gx = 0.5f + 0.5f * tanh_fast(0.5f * (li + bi));
        // ga: tighter sigmoid (feeds decay exponent)
        float ga = __fdividef(1.0f, 1.0f + __expf(-(la + ba)));
        float log_a = ga * sp8;
        float a = rs ? 0.0f : __expf(log_a);
        float a2 = a * a;
        float mult = rs ? 1.0f : sqrt_fast(fmaxf(1.0f - a2, 0.0f));
        float nx = co * gx * mult;
        size_t o = (size_t)m * DDIM + d;
        g_a[o] = a;
        g_nxs[o] = __float2half(nx);
        H = fmaf(a, H, nx);
        A *= a;
    }
    int o = (b * NC + c) * DDIM + d;
    g_Aag[o] = A;
    g_Hag[o] = H;
}

// ---------------- cross-chunk scan ----------------
__global__ __launch_bounds__(256) void scan_phase2(const float* __restrict__ prev_h) {
    int t = blockIdx.x * 256 + threadIdx.x;
    if (t >= 2 * DDIM) return;
    int b = t / DDIM, d = t % DDIM;
    float h = prev_h[t];
#pragma unroll
    for (int c = 0; c < NC; c++) {
        int o = (b * NC + c) * DDIM + d;
        g_Hin[o] = h;
        h = fmaf(g_Aag[o], h, g_Hag[o]);
    }
}

__global__ __launch_bounds__(256) void scan_phase3() {
    int d = blockIdx.x * 256 + threadIdx.x;
    int c = blockIdx.y;
    int b = blockIdx.z;
    int base = (b * SEQB + c * CL) * DDIM + d;
    float h = g_Hin[(b * NC + c) * DDIM + d];
#pragma unroll 4
    for (int i = 0; i < CL; i++) {
        int o = base + i * DDIM;
        float a = g_a[o];
        float x = __half2float(g_nxs[o]);
        h = fmaf(a, h, x);
        g_nxh[o] = __float2half(h * __half2float(g_ybh[o]));
    }
}

// ---------------- launcher ----------------
extern "C" void kernel_launch(void* const* d_in, const int* in_sizes, int n_in,
                              void* d_out, int out_size) {
    const float* x_in    = (const float*)d_in[0];
    const int*   pos     = (const int*)d_in[1];
    const float* prev_h  = (const float*)d_in[2];
    const float* w_y     = (const float*)d_in[3];
    const float* b_y     = (const float*)d_in[4];
    const float* w_x     = (const float*)d_in[5];
    const float* b_x     = (const float*)d_in[6];
    const float* w_out   = (const float*)d_in[7];
    const float* b_out   = (const float*)d_in[8];
    const float* conv_w  = (const float*)d_in[9];
    const float* conv_b  = (const float*)d_in[10];
    const float* a_param = (const float*)d_in[11];
    const float* ig_w    = (const float*)d_in[12];
    const float* ig_b    = (const float*)d_in[13];
    const float* ag_w    = (const float*)d_in[14];
    const float* ag_b    = (const float*)d_in[15];
    float* out = (float*)d_out;

    __half *p_xh, *p_coh, *p_nxh, *p_wch, *p_woh, *p_gwh;
    cudaGetSymbolAddress((void**)&p_xh,  g_xh);
    cudaGetSymbolAddress((void**)&p_coh, g_coh);
    cudaGetSymbolAddress((void**)&p_nxh, g_nxh);
    cudaGetSymbolAddress((void**)&p_wch, g_wch);
    cudaGetSymbolAddress((void**)&p_woh, g_woh);
    cudaGetSymbolAddress((void**)&p_gwh, g_gwh);

    cudaFuncSetAttribute(gemm_f16, cudaFuncAttributeMaxDynamicSharedMemorySize, GSMEM);

    reset_kernel<<<(TOK + 255) / 256, 256>>>(pos);

    // fp32 -> fp16 conversions
    const int WN4 = DDIM * DDIM / 4;
    const int XN4 = TOK * DDIM / 4;
    const int GN4 = 2560 * BW / 4;
    f2h_kernel<<<(XN4 + 255) / 256, 256>>>(x_in, p_xh, XN4);
    f2h_kernel<<<(WN4 + 255) / 256, 256>>>(w_x, p_wch, WN4);
    f2h_kernel<<<(WN4 + 255) / 256, 256>>>(w_y, p_wch + (size_t)DDIM * DDIM, WN4);
    f2h_kernel<<<(WN4 + 255) / 256, 256>>>(w_out, p_woh, WN4);
    f2h_kernel<<<(GN4 + 255) / 256, 256>>>(ig_w, p_gwh, GN4);
    f2h_kernel<<<(GN4 + 255) / 256, 256>>>(ag_w, p_gwh + (size_t)2560 * BW, GN4);

    // combined x/y GEMM (N = 5120): writes g_xbh (fp16) and g_ybh (fp16, gelu)
    dim3 gxy(NGATE / 256, TOK / 128);   // (20, 64)
    gemm_f16<<<gxy, 256, GSMEM>>>(p_xh, p_wch, b_x, b_y, nullptr, DDIM, DDIM, 0, 1);

    // conv (fp16 in, fp16 out)
    conv_kernel<<<(2 * (SEQB / 4) * (DDIM / 4) + 255) / 256, 256>>>(conv_w, conv_b);

    // gates GEMM (both gates, K=256) -> fp16 logits
    gemm_f16<<<gxy, 256, GSMEM>>>(p_coh, p_gwh, nullptr, nullptr, nullptr, BW, BW, 0, 2);

    // fused pointwise + chunk-scan, cross-chunk scan, fix-up
    rglru_scan1<<<dim3(DDIM / 256, NC, 2), 256>>>(ig_b, ag_b, a_param);
    scan_phase2<<<(2 * DDIM + 255) / 256, 256>>>(prev_h);
    scan_phase3<<<dim3(DDIM / 256, NC, 2), 256>>>();

    // final GEMM
    dim3 gf(DDIM / 256, TOK / 128);     // (10, 64)
    gemm_f16<<<gf, 256, GSMEM>>>(p_nxh, p_woh, b_out, nullptr, out, DDIM, DDIM, DDIM, 0);
}